// round 7
// baseline (speedup 1.0000x reference)
#include <cuda_runtime.h>
#include <cuda_bf16.h>
#include <cstdint>

#define B_SZ 1024
#define E_SZ 512
#define C_SZ 16384

// ---------------- scratch (static device memory; no runtime alloc) ----------------
__device__ int8_t g_proxyQ[C_SZ * E_SZ];   // normalized+quantized proxies
__device__ int8_t g_inputQ[B_SZ * E_SZ];   // quantized inputs
__device__ float g_scaleB_arr[C_SZ];       // per-proxy-row scale
__device__ float g_scaleA_arr[B_SZ];       // per-input-row scale
__device__ float g_outlier[C_SZ];
__device__ float g_invEff[C_SZ];
__device__ float g_Spos[C_SZ];
__device__ float g_Sneg[C_SZ];
__device__ float g_Nsum[C_SZ];

// ---------------- fast exp on FMA pipe ----------------
__device__ __forceinline__ float fexp(float x) {
    float t = x * 1.44269504088896341f;
    float fi = rintf(t);
    float f = t - fi;
    float p = 1.54035303933816e-4f;
    p = fmaf(p, f, 1.33335581467049e-3f);
    p = fmaf(p, f, 9.61812910762848e-3f);
    p = fmaf(p, f, 5.55041086648216e-2f);
    p = fmaf(p, f, 2.40226506959101e-1f);
    p = fmaf(p, f, 6.93147180559945e-1f);
    p = fmaf(p, f, 1.0f);
    int i = (int)fi;
    float s = __int_as_float((i + 127) << 23);
    return p * s;
}

// ---------------- fused prep kernel (no cross-block dependencies) ----------------
// blocks 0..2175 : row normalize + int8 quantize (8 rows/block, warp per row)
//                  rows 0..16383 = proxies, rows 16384..17407 = inputs
// blocks 2176..2239: per-class constants + accumulator zero
__global__ void __launch_bounds__(256) prepKernel(
    const float* __restrict__ inputs,
    const float* __restrict__ proxies, const float* __restrict__ effN,
    const float* __restrict__ ls)
{
    const int b = blockIdx.x;
    const int tid = threadIdx.x;
    if (b < 2176) {
        int row = b * 8 + (tid >> 5);
        int lane = tid & 31;
        bool isProxy = row < C_SZ;
        int drow = isProxy ? row : row - C_SZ;
        const float4* p4 = (const float4*)(isProxy ? proxies + (size_t)row * E_SZ
                                                   : inputs + (size_t)drow * E_SZ);
        float4 v[4];
        float s = 0.0f;
#pragma unroll
        for (int j = 0; j < 4; j++) {
            v[j] = p4[lane + j * 32];
            s += v[j].x * v[j].x + v[j].y * v[j].y + v[j].z * v[j].z + v[j].w * v[j].w;
        }
#pragma unroll
        for (int o = 16; o > 0; o >>= 1) s += __shfl_xor_sync(0xffffffffu, s, o);
        float rn = rsqrtf(s + 1e-12f);
        float m = 0.0f;
#pragma unroll
        for (int j = 0; j < 4; j++) {
            m = fmaxf(m, fabsf(v[j].x)); m = fmaxf(m, fabsf(v[j].y));
            m = fmaxf(m, fabsf(v[j].z)); m = fmaxf(m, fabsf(v[j].w));
        }
        m *= rn;
#pragma unroll
        for (int o = 16; o > 0; o >>= 1) m = fmaxf(m, __shfl_xor_sync(0xffffffffu, m, o));
        float scale = m * (1.0f / 127.0f);
        float qmul = rn * 127.0f / fmaxf(m, 1e-20f);
        uint32_t* dst = (uint32_t*)(isProxy ? g_proxyQ : g_inputQ) + (size_t)drow * 128;
#pragma unroll
        for (int j = 0; j < 4; j++) {
            int x0 = max(-127, min(127, __float2int_rn(v[j].x * qmul)));
            int x1 = max(-127, min(127, __float2int_rn(v[j].y * qmul)));
            int x2 = max(-127, min(127, __float2int_rn(v[j].z * qmul)));
            int x3 = max(-127, min(127, __float2int_rn(v[j].w * qmul)));
            dst[lane + j * 32] = (uint32_t)(x0 & 255) | ((uint32_t)(x1 & 255) << 8) |
                                 ((uint32_t)(x2 & 255) << 16) | ((uint32_t)(x3 & 255) << 24);
        }
        if (lane == 0) {
            if (isProxy) g_scaleB_arr[drow] = scale;
            else         g_scaleA_arr[drow] = scale;
        }
    } else {
        int c = (b - 2176) * 256 + tid;
        float eff = effN[c], l = ls[c];
        float wb = 1.0f / (1.0f + log1pf(eff));
        float eta = (1.0f + (1.0f - l)) * wb + 0.1f;   // K=1, LAM=0.1
        g_outlier[c] = l - eta;
        g_invEff[c] = 1.0f / fmaxf(1.0f, eff);
        g_Spos[c] = 0.0f;
        g_Sneg[c] = 0.0f;
        g_Nsum[c] = 0.0f;
    }
}

// ---------------- IMMA helpers ----------------
__device__ __forceinline__ uint32_t smem_u32(const void* p) {
    uint32_t a;
    asm("{ .reg .u64 t; cvta.to.shared.u64 t, %1; cvt.u32.u64 %0, t; }" : "=r"(a) : "l"(p));
    return a;
}
__device__ __forceinline__ void mma_s8(int* d, const uint32_t* a, const uint32_t* b) {
    asm volatile(
        "mma.sync.aligned.m16n8k32.row.col.s32.s8.s8.s32 "
        "{%0,%1,%2,%3}, {%4,%5,%6,%7}, {%8,%9}, {%0,%1,%2,%3};\n"
        : "+r"(d[0]), "+r"(d[1]), "+r"(d[2]), "+r"(d[3])
        : "r"(a[0]), "r"(a[1]), "r"(a[2]), "r"(a[3]), "r"(b[0]), "r"(b[1]));
}
#define LDSM_X4(r, a) \
    asm volatile("ldmatrix.sync.aligned.m8n8.x4.shared.b16 {%0,%1,%2,%3}, [%4];" \
        : "=r"((r)[0]), "=r"((r)[1]), "=r"((r)[2]), "=r"((r)[3]) : "r"(a))

__device__ __forceinline__ void cpa16(uint32_t s, const void* g) {
    asm volatile("cp.async.cg.shared.global [%0], [%1], 16;" :: "r"(s), "l"(g));
}
#define CP_COMMIT() asm volatile("cp.async.commit_group;" ::: "memory")

// row r (128B rows), 16B granule g (0..7): xor swizzle
#define SWZ(r, g) ((r) * 128 + (((g) ^ ((r) & 7)) << 4))

// ---------------- persistent main IMMA kernel ----------------
// Tiles: 128x128; tile id t: cBase=(t&127)*128, mBase=(t>>7)*128; 1024 tiles.
// Grid = 296 persistent CTAs (2/SM). K chunks of 128 int8 (4 per tile),
// 3-stage cp.async ring, prefetch distance 2, one syncthreads per chunk.
#define GRID_MAIN 296
#define NTILES    1024

#define SM_TGT   0       // int   [2][128]
#define SM_OUTL  1024    // float [2][128]
#define SM_IE    2048    // float [2][128]
#define SM_SA    3072    // float [2][128] row scales
#define SM_SB    4096    // float [2][128] col scales
#define SM_STG   5120    // 3 stages x (A 16KB + B 16KB)
#define SM_BYTES 103424

__global__ void __launch_bounds__(256, 2) mainIMMA(const int* __restrict__ targets) {
    extern __shared__ __align__(1024) char sm[];
    const uint32_t smb = smem_u32(sm);
    const int tid = threadIdx.x;
    const int lane = tid & 31;
    const int warp = tid >> 5;
    const int warpM = warp >> 2;   // 0..1 (64 rows each)
    const int warpN = warp & 3;    // 0..3 (32 cols each)
    const int bid = blockIdx.x;

    const int NT = (NTILES - bid + GRID_MAIN - 1) / GRID_MAIN;   // tiles this CTA
    const int NT4 = NT * 4;

    int acc[4][4][4];
#pragma unroll
    for (int i = 0; i < 4; i++)
#pragma unroll
        for (int j = 0; j < 4; j++)
#pragma unroll
            for (int e = 0; e < 4; e++) acc[i][j][e] = 0;

    // prefetch global chunk gg (tile bid + (gg>>2)*296, k-chunk gg&3) into stage gg%3
#define PREFETCH(gg) do { \
        const int T_ = (gg) >> 2, k_ = (gg) & 3; \
        const int tt_ = bid + T_ * GRID_MAIN; \
        const int cB_ = (tt_ & 127) << 7, mB_ = (tt_ >> 7) << 7; \
        const int kOff_ = k_ * 128; \
        const uint32_t stg_ = smb + SM_STG + ((gg) % 3) * 32768; \
        _Pragma("unroll") \
        for (int i_ = 0; i_ < 4; i_++) { \
            int idx_ = tid + i_ * 256; int r_ = idx_ >> 3, q_ = idx_ & 7; \
            cpa16(stg_ + SWZ(r_, q_), \
                  g_inputQ + (size_t)(mB_ + r_) * E_SZ + kOff_ + q_ * 16); \
        } \
        _Pragma("unroll") \
        for (int i_ = 0; i_ < 4; i_++) { \
            int idx_ = tid + i_ * 256; int r_ = idx_ >> 3, q_ = idx_ & 7; \
            cpa16(stg_ + 16384 + SWZ(r_, q_), \
                  g_proxyQ + (size_t)(cB_ + r_) * E_SZ + kOff_ + q_ * 16); \
        } \
        if (k_ == 0) { \
            int par_ = (T_ & 1) << 9; \
            if (tid < 32)        cpa16(smb + SM_TGT  + par_ + tid * 16,         targets      + mB_ + tid * 4); \
            else if (tid < 64)   cpa16(smb + SM_OUTL + par_ + (tid - 32) * 16,  g_outlier    + cB_ + (tid - 32) * 4); \
            else if (tid < 96)   cpa16(smb + SM_IE   + par_ + (tid - 64) * 16,  g_invEff     + cB_ + (tid - 64) * 4); \
            else if (tid < 128)  cpa16(smb + SM_SA   + par_ + (tid - 96) * 16,  g_scaleA_arr + mB_ + (tid - 96) * 4); \
            else if (tid < 160)  cpa16(smb + SM_SB   + par_ + (tid - 128) * 16, g_scaleB_arr + cB_ + (tid - 128) * 4); \
        } \
        CP_COMMIT(); \
    } while (0)

    PREFETCH(0);
    if (NT4 > 1) PREFETCH(1);

#pragma unroll 1
    for (int g = 0; g < NT4; g++) {
        if (g < NT4 - 1) { asm volatile("cp.async.wait_group 1;" ::: "memory"); }
        else             { asm volatile("cp.async.wait_group 0;" ::: "memory"); }
        __syncthreads();
        if (g + 2 < NT4) PREFETCH(g + 2);

        const uint32_t aBase = smb + SM_STG + (g % 3) * 32768;
        const uint32_t bBase = aBase + 16384;
#pragma unroll
        for (int ks = 0; ks < 4; ks++) {
            uint32_t a[4][4], bfr[2][4];
#pragma unroll
            for (int mt = 0; mt < 4; mt++) {
                int r = warpM * 64 + mt * 16 + (lane & 15);
                int q = ks * 2 + (lane >> 4);
                LDSM_X4(a[mt], aBase + SWZ(r, q));
            }
#pragma unroll
            for (int np = 0; np < 2; np++) {
                int n = warpN * 32 + np * 16 + ((lane >> 4) << 3) + (lane & 7);
                int q = ks * 2 + ((lane >> 3) & 1);
                LDSM_X4(bfr[np], bBase + SWZ(n, q));
            }
#pragma unroll
            for (int mt = 0; mt < 4; mt++)
#pragma unroll
                for (int nt = 0; nt < 4; nt++)
                    mma_s8(acc[mt][nt], a[mt], &bfr[nt >> 1][(nt & 1) * 2]);
        }

        if ((g & 3) == 3) {
            // ---- epilogue for tile T = g>>2 ----
            const int T = g >> 2;
            const int tt = bid + T * GRID_MAIN;
            const int cBase = (tt & 127) << 7;
            const int par = (T & 1) << 7;
            const int* shTgt = (const int*)(sm + SM_TGT) + par;
            const float* shOutl = (const float*)(sm + SM_OUTL) + par;
            const float* shIE = (const float*)(sm + SM_IE) + par;
            const float* shSA = (const float*)(sm + SM_SA) + par;
            const float* shSB = (const float*)(sm + SM_SB) + par;

            int tg[4][2];
            float sAr[4][2];
#pragma unroll
            for (int mt = 0; mt < 4; mt++) {
                int rl = warpM * 64 + mt * 16 + (lane >> 2);
                tg[mt][0] = shTgt[rl];
                tg[mt][1] = shTgt[rl + 8];
                sAr[mt][0] = shSA[rl];
                sAr[mt][1] = shSA[rl + 8];
            }
#pragma unroll
            for (int nt = 0; nt < 4; nt++) {
#pragma unroll
                for (int p = 0; p < 2; p++) {
                    int cc = warpN * 32 + nt * 8 + (lane & 3) * 2 + p;
                    float outl = shOutl[cc];
                    float ie = shIE[cc];
                    float sb = shSB[cc];
                    int clsG = cBase + cc;
                    float sP = 0.0f, sN = 0.0f, sV = 0.0f;
#pragma unroll
                    for (int mt = 0; mt < 4; mt++) {
#pragma unroll
                        for (int h = 0; h < 2; h++) {
                            float cv = (float)acc[mt][nt][h * 2 + p] * sAr[mt][h] * sb;
                            if (tg[mt][h] == clsG) {
                                sP += fexp(32.0f * (0.1f - cv));
                            } else {
                                float nv = (cv < outl) ? ie : 1.0f;
                                sV += nv;
                                sN += fexp(32.0f * (cv + 0.1f) * nv);
                            }
                        }
                    }
#pragma unroll
                    for (int o = 4; o <= 16; o <<= 1) {
                        sP += __shfl_xor_sync(0xffffffffu, sP, o);
                        sN += __shfl_xor_sync(0xffffffffu, sN, o);
                        sV += __shfl_xor_sync(0xffffffffu, sV, o);
                    }
                    if ((lane >> 2) == 0) {
                        atomicAdd(&g_Spos[clsG], sP);
                        atomicAdd(&g_Sneg[clsG], sN);
                        atomicAdd(&g_Nsum[clsG], sV);
                    }
                }
            }
            // reset accumulators for next tile
#pragma unroll
            for (int i = 0; i < 4; i++)
#pragma unroll
                for (int j = 0; j < 4; j++)
#pragma unroll
                    for (int e = 0; e < 4; e++) acc[i][j][e] = 0;
        }
    }
}

// ---------------- finalize (single block: race-free shared histogram) ----------------
#define FIN_SMEM (C_SZ * 4)
__global__ void __launch_bounds__(1024) finalizeKernel(const int* __restrict__ targets,
                                                       float* __restrict__ out) {
    extern __shared__ int scnt[];
    __shared__ float smr[4][1024];
    int tid = threadIdx.x;
    for (int c = tid; c < C_SZ; c += 1024) scnt[c] = 0;
    __syncthreads();
    atomicAdd(&scnt[targets[tid]], 1);   // blockDim == B_SZ == 1024
    __syncthreads();

    float posT = 0.0f, negT = 0.0f, posW = 0.0f, negW = 0.0f;
    for (int c = tid; c < C_SZ; c += 1024) {
        int cnt = scnt[c];
        if (cnt > 0) { posW += 1.0f; posT += log1pf(g_Spos[c]); }
        negT += log1pf(g_Sneg[c]);
        int Ncnt = B_SZ - cnt;
        float nm = g_Nsum[c] / fmaxf((float)Ncnt, 1.0f);
        if (Ncnt > 0) negW += nm;
    }
    smr[0][tid] = posT; smr[1][tid] = negT; smr[2][tid] = posW; smr[3][tid] = negW;
    __syncthreads();
    for (int s = 512; s > 0; s >>= 1) {
        if (tid < s) {
#pragma unroll
            for (int j = 0; j < 4; j++) smr[j][tid] += smr[j][tid + s];
        }
        __syncthreads();
    }
    if (tid == 0) out[0] = smr[0][0] / smr[2][0] + smr[1][0] / smr[3][0];
}

// ---------------- launch ----------------
extern "C" void kernel_launch(void* const* d_in, const int* in_sizes, int n_in,
                              void* d_out, int out_size) {
    const float* inputs  = (const float*)d_in[0];   // [B,E] f32
    const int*   targets = (const int*)d_in[1];     // [B]   i32
    const float* proxies = (const float*)d_in[2];   // [C,E] f32
    const float* effN    = (const float*)d_in[3];   // [C]
    const float* ls      = (const float*)d_in[4];   // [C]
    float* out = (float*)d_out;

    cudaFuncSetAttribute(mainIMMA, cudaFuncAttributeMaxDynamicSharedMemorySize, SM_BYTES);
    cudaFuncSetAttribute(finalizeKernel, cudaFuncAttributeMaxDynamicSharedMemorySize, FIN_SMEM);

    prepKernel<<<2240, 256>>>(inputs, proxies, effN, ls);
    mainIMMA<<<GRID_MAIN, 256, SM_BYTES>>>(targets);
    finalizeKernel<<<1, 1024, FIN_SMEM>>>(targets, out);
}

// round 8
// speedup vs baseline: 1.2677x; 1.2677x over previous
#include <cuda_runtime.h>
#include <cuda_fp16.h>
#include <cstdint>

#define B_SZ 1024
#define E_SZ 512
#define C_SZ 16384

// ---------------- scratch (static device memory; no runtime alloc) ----------------
__device__ __half g_proxyH[C_SZ * E_SZ];   // normalized proxies, f16
__device__ __half g_inputH[B_SZ * E_SZ];   // inputs, f16
__device__ float g_outlier[C_SZ];
__device__ float g_invEff[C_SZ];
__device__ float g_Spos[C_SZ];
__device__ float g_Sneg[C_SZ];
__device__ float g_Nsum[C_SZ];

// ---------------- fast exp on FMA pipe ----------------
__device__ __forceinline__ float fexp(float x) {
    float t = x * 1.44269504088896341f;
    float fi = rintf(t);
    float f = t - fi;
    float p = 1.54035303933816e-4f;
    p = fmaf(p, f, 1.33335581467049e-3f);
    p = fmaf(p, f, 9.61812910762848e-3f);
    p = fmaf(p, f, 5.55041086648216e-2f);
    p = fmaf(p, f, 2.40226506959101e-1f);
    p = fmaf(p, f, 6.93147180559945e-1f);
    p = fmaf(p, f, 1.0f);
    int i = (int)fi;
    float s = __int_as_float((i + 127) << 23);
    return p * s;
}

// ---------------- fused prep kernel (no cross-block dependencies) ----------------
// blocks 0..2047   : proxy L2-norm + f16 (8 rows per block, 1 warp/row)
// blocks 2048..2559: input f32->f16 (1 float4/thread)
// blocks 2560..2623: per-class constants + accumulator zero
__global__ void __launch_bounds__(256) prepKernel(
    const float* __restrict__ inputs,
    const float* __restrict__ proxies, const float* __restrict__ effN,
    const float* __restrict__ ls)
{
    const int b = blockIdx.x;
    const int tid = threadIdx.x;
    if (b < 2048) {
        int row = b * 8 + (tid >> 5);
        int lane = tid & 31;
        const float4* p4 = (const float4*)(proxies + (size_t)row * E_SZ);
        float4 v[4];
        float s = 0.0f;
#pragma unroll
        for (int j = 0; j < 4; j++) {
            v[j] = p4[lane + j * 32];
            s += v[j].x * v[j].x + v[j].y * v[j].y + v[j].z * v[j].z + v[j].w * v[j].w;
        }
#pragma unroll
        for (int o = 16; o > 0; o >>= 1) s += __shfl_xor_sync(0xffffffffu, s, o);
        float rn = rsqrtf(s + 1e-12f);
        __half2* out = (__half2*)(g_proxyH + (size_t)row * E_SZ);
#pragma unroll
        for (int j = 0; j < 4; j++) {
            out[(lane + j * 32) * 2]     = __float22half2_rn(make_float2(v[j].x * rn, v[j].y * rn));
            out[(lane + j * 32) * 2 + 1] = __float22half2_rn(make_float2(v[j].z * rn, v[j].w * rn));
        }
    } else if (b < 2560) {
        int i = (b - 2048) * 256 + tid;          // over B*E/4 float4s
        float4 v = ((const float4*)inputs)[i];
        __half2* o = (__half2*)g_inputH;
        o[i * 2]     = __float22half2_rn(make_float2(v.x, v.y));
        o[i * 2 + 1] = __float22half2_rn(make_float2(v.z, v.w));
    } else {
        int c = (b - 2560) * 256 + tid;
        float eff = effN[c], l = ls[c];
        float wb = 1.0f / (1.0f + log1pf(eff));
        float eta = (1.0f + (1.0f - l)) * wb + 0.1f;   // K=1, LAM=0.1
        g_outlier[c] = l - eta;
        g_invEff[c] = 1.0f / fmaxf(1.0f, eff);
        g_Spos[c] = 0.0f;
        g_Sneg[c] = 0.0f;
        g_Nsum[c] = 0.0f;
    }
}

// ---------------- HMMA helpers ----------------
__device__ __forceinline__ uint32_t smem_u32(const void* p) {
    uint32_t a;
    asm("{ .reg .u64 t; cvta.to.shared.u64 t, %1; cvt.u32.u64 %0, t; }" : "=r"(a) : "l"(p));
    return a;
}
// f16 inputs, f16 accumulators (D/C = 2 regs of half2)
__device__ __forceinline__ void mma_f16(uint32_t* d, const uint32_t* a, const uint32_t* b) {
    asm volatile(
        "mma.sync.aligned.m16n8k16.row.col.f16.f16.f16.f16 "
        "{%0,%1}, {%2,%3,%4,%5}, {%6,%7}, {%0,%1};\n"
        : "+r"(d[0]), "+r"(d[1])
        : "r"(a[0]), "r"(a[1]), "r"(a[2]), "r"(a[3]), "r"(b[0]), "r"(b[1]));
}
#define LDSM_X4(r, a) \
    asm volatile("ldmatrix.sync.aligned.m8n8.x4.shared.b16 {%0,%1,%2,%3}, [%4];" \
        : "=r"((r)[0]), "=r"((r)[1]), "=r"((r)[2]), "=r"((r)[3]) : "r"(a))

__device__ __forceinline__ void cpa16(uint32_t s, const void* g) {
    asm volatile("cp.async.cg.shared.global [%0], [%1], 16;" :: "r"(s), "l"(g));
}
#define CP_COMMIT() asm volatile("cp.async.commit_group;" ::: "memory")

// row r (128B rows), 16B granule g (0..7): xor swizzle
#define SWZ(r, g) ((r) * 128 + (((g) ^ ((r) & 7)) << 4))

// ---------------- persistent main HMMA kernel ----------------
// Tiles: 128x128, tile id t: cBase=(t&127)*128, mBase=(t>>7)*128; 1024 tiles.
// Grid = 296 persistent CTAs (2/SM). K chunks of 64 (8 per tile),
// 3-stage cp.async ring, prefetch distance 2, one syncthreads per chunk.
#define GRID_MAIN 296
#define NTILES    1024

#define SM_TGT   0       // int [2][128]
#define SM_OUTL  1024    // float [2][128]
#define SM_IE    2048    // float [2][128]
#define SM_STG   3072    // 3 stages x (A 16KB + B 16KB)
#define SM_BYTES 101376

__global__ void __launch_bounds__(256, 2) mainHMMA(const int* __restrict__ targets) {
    extern __shared__ __align__(1024) char sm[];
    const uint32_t smb = smem_u32(sm);
    const int tid = threadIdx.x;
    const int lane = tid & 31;
    const int warp = tid >> 5;
    const int warpM = warp >> 2;   // 0..1 (64 rows each)
    const int warpN = warp & 3;    // 0..3 (32 cols each)
    const int bid = blockIdx.x;

    const int NT = (NTILES - bid + GRID_MAIN - 1) / GRID_MAIN;   // tiles this CTA
    const int NT8 = NT * 8;

    uint32_t acc[4][4][2];
#pragma unroll
    for (int i = 0; i < 4; i++)
#pragma unroll
        for (int j = 0; j < 4; j++) { acc[i][j][0] = 0u; acc[i][j][1] = 0u; }

    // prefetch global chunk gg (tile bid + (gg>>3)*296, k-chunk gg&7) into stage gg%3
#define PREFETCH(gg) do { \
        const int T_ = (gg) >> 3, k_ = (gg) & 7; \
        const int tt_ = bid + T_ * GRID_MAIN; \
        const int cB_ = (tt_ & 127) << 7, mB_ = (tt_ >> 7) << 7; \
        const int kOff_ = k_ * 64; \
        const uint32_t stg_ = smb + SM_STG + ((gg) % 3) * 32768; \
        _Pragma("unroll") \
        for (int i_ = 0; i_ < 4; i_++) { \
            int idx_ = tid + i_ * 256; int r_ = idx_ >> 3, q_ = idx_ & 7; \
            cpa16(stg_ + SWZ(r_, q_), \
                  g_inputH + (size_t)(mB_ + r_) * E_SZ + kOff_ + q_ * 8); \
        } \
        _Pragma("unroll") \
        for (int i_ = 0; i_ < 4; i_++) { \
            int idx_ = tid + i_ * 256; int r_ = idx_ >> 3, q_ = idx_ & 7; \
            cpa16(stg_ + 16384 + SWZ(r_, q_), \
                  g_proxyH + (size_t)(cB_ + r_) * E_SZ + kOff_ + q_ * 8); \
        } \
        if (k_ == 0) { \
            int par_ = (T_ & 1) << 9; \
            if (tid < 32)       cpa16(smb + SM_TGT  + par_ + tid * 16,        targets   + mB_ + tid * 4); \
            else if (tid < 64)  cpa16(smb + SM_OUTL + par_ + (tid - 32) * 16, g_outlier + cB_ + (tid - 32) * 4); \
            else if (tid < 96)  cpa16(smb + SM_IE   + par_ + (tid - 64) * 16, g_invEff  + cB_ + (tid - 64) * 4); \
        } \
        CP_COMMIT(); \
    } while (0)

    PREFETCH(0);
    if (NT8 > 1) PREFETCH(1);

#pragma unroll 1
    for (int g = 0; g < NT8; g++) {
        if (g < NT8 - 1) { asm volatile("cp.async.wait_group 1;" ::: "memory"); }
        else             { asm volatile("cp.async.wait_group 0;" ::: "memory"); }
        __syncthreads();
        if (g + 2 < NT8) PREFETCH(g + 2);

        const uint32_t aBase = smb + SM_STG + (g % 3) * 32768;
        const uint32_t bBase = aBase + 16384;
#pragma unroll
        for (int ks = 0; ks < 4; ks++) {
            uint32_t a[4][4], bfr[2][4];
#pragma unroll
            for (int mt = 0; mt < 4; mt++) {
                int r = warpM * 64 + mt * 16 + (lane & 15);
                int q = ks * 2 + (lane >> 4);
                LDSM_X4(a[mt], aBase + SWZ(r, q));
            }
#pragma unroll
            for (int np = 0; np < 2; np++) {
                int n = warpN * 32 + np * 16 + ((lane >> 4) << 3) + (lane & 7);
                int q = ks * 2 + ((lane >> 3) & 1);
                LDSM_X4(bfr[np], bBase + SWZ(n, q));
            }
#pragma unroll
            for (int mt = 0; mt < 4; mt++)
#pragma unroll
                for (int nt = 0; nt < 4; nt++)
                    mma_f16(acc[mt][nt], a[mt], &bfr[nt >> 1][(nt & 1) * 2]);
        }

        if ((g & 7) == 7) {
            // ---- epilogue for tile T = g>>3 ----
            const int T = g >> 3;
            const int tt = bid + T * GRID_MAIN;
            const int cBase = (tt & 127) << 7;
            const int par = (T & 1) << 7;
            const int* shTgt = (const int*)(sm + SM_TGT) + par;
            const float* shOutl = (const float*)(sm + SM_OUTL) + par;
            const float* shIE = (const float*)(sm + SM_IE) + par;

            int tg[4][2];
#pragma unroll
            for (int mt = 0; mt < 4; mt++) {
                int rl = warpM * 64 + mt * 16 + (lane >> 2);
                tg[mt][0] = shTgt[rl];
                tg[mt][1] = shTgt[rl + 8];
            }
#pragma unroll
            for (int nt = 0; nt < 4; nt++) {
#pragma unroll
                for (int p = 0; p < 2; p++) {
                    int cc = warpN * 32 + nt * 8 + (lane & 3) * 2 + p;
                    float outl = shOutl[cc];
                    float ie = shIE[cc];
                    int clsG = cBase + cc;
                    float sP = 0.0f, sN = 0.0f, sV = 0.0f;
#pragma unroll
                    for (int mt = 0; mt < 4; mt++) {
#pragma unroll
                        for (int h = 0; h < 2; h++) {
                            float2 f2 = __half22float2(*(const __half2*)&acc[mt][nt][h]);
                            float cv = p ? f2.y : f2.x;
                            if (tg[mt][h] == clsG) {
                                sP += fexp(32.0f * (0.1f - cv));
                            } else {
                                float nv = (cv < outl) ? ie : 1.0f;
                                sV += nv;
                                sN += fexp(32.0f * (cv + 0.1f) * nv);
                            }
                        }
                    }
#pragma unroll
                    for (int o = 4; o <= 16; o <<= 1) {
                        sP += __shfl_xor_sync(0xffffffffu, sP, o);
                        sN += __shfl_xor_sync(0xffffffffu, sN, o);
                        sV += __shfl_xor_sync(0xffffffffu, sV, o);
                    }
                    if ((lane >> 2) == 0) {
                        atomicAdd(&g_Spos[clsG], sP);
                        atomicAdd(&g_Sneg[clsG], sN);
                        atomicAdd(&g_Nsum[clsG], sV);
                    }
                }
            }
            // reset accumulators for next tile
#pragma unroll
            for (int i = 0; i < 4; i++)
#pragma unroll
                for (int j = 0; j < 4; j++) { acc[i][j][0] = 0u; acc[i][j][1] = 0u; }
        }
    }
}

// ---------------- finalize (single block: race-free shared histogram) ----------------
#define FIN_SMEM (C_SZ * 4)
__global__ void __launch_bounds__(1024) finalizeKernel(const int* __restrict__ targets,
                                                       float* __restrict__ out) {
    extern __shared__ int scnt[];
    __shared__ float smr[4][1024];
    int tid = threadIdx.x;
    for (int c = tid; c < C_SZ; c += 1024) scnt[c] = 0;
    __syncthreads();
    atomicAdd(&scnt[targets[tid]], 1);   // blockDim == B_SZ == 1024
    __syncthreads();

    float posT = 0.0f, negT = 0.0f, posW = 0.0f, negW = 0.0f;
    for (int c = tid; c < C_SZ; c += 1024) {
        int cnt = scnt[c];
        if (cnt > 0) { posW += 1.0f; posT += log1pf(g_Spos[c]); }
        negT += log1pf(g_Sneg[c]);
        int Ncnt = B_SZ - cnt;
        float nm = g_Nsum[c] / fmaxf((float)Ncnt, 1.0f);
        if (Ncnt > 0) negW += nm;
    }
    smr[0][tid] = posT; smr[1][tid] = negT; smr[2][tid] = posW; smr[3][tid] = negW;
    __syncthreads();
    for (int s = 512; s > 0; s >>= 1) {
        if (tid < s) {
#pragma unroll
            for (int j = 0; j < 4; j++) smr[j][tid] += smr[j][tid + s];
        }
        __syncthreads();
    }
    if (tid == 0) out[0] = smr[0][0] / smr[2][0] + smr[1][0] / smr[3][0];
}

// ---------------- launch ----------------
extern "C" void kernel_launch(void* const* d_in, const int* in_sizes, int n_in,
                              void* d_out, int out_size) {
    const float* inputs  = (const float*)d_in[0];   // [B,E] f32
    const int*   targets = (const int*)d_in[1];     // [B]   i32
    const float* proxies = (const float*)d_in[2];   // [C,E] f32
    const float* effN    = (const float*)d_in[3];   // [C]
    const float* ls      = (const float*)d_in[4];   // [C]
    float* out = (float*)d_out;

    cudaFuncSetAttribute(mainHMMA, cudaFuncAttributeMaxDynamicSharedMemorySize, SM_BYTES);
    cudaFuncSetAttribute(finalizeKernel, cudaFuncAttributeMaxDynamicSharedMemorySize, FIN_SMEM);

    prepKernel<<<2624, 256>>>(inputs, proxies, effN, ls);
    mainHMMA<<<GRID_MAIN, 256, SM_BYTES>>>(targets);
    finalizeKernel<<<1, 1024, FIN_SMEM>>>(targets, out);
}

// round 9
// speedup vs baseline: 1.2697x; 1.0016x over previous
#include <cuda_runtime.h>
#include <cuda_bf16.h>
#include <cstdint>

#define B_SZ 1024
#define E_SZ 512
#define C_SZ 16384

// ---------------- scratch (static device memory; no runtime alloc) ----------------
__device__ __nv_bfloat16 g_proxyB[C_SZ * E_SZ];   // normalized proxies, bf16
__device__ __nv_bfloat16 g_inputB[B_SZ * E_SZ];   // inputs, bf16
__device__ float g_outlier[C_SZ];
__device__ float g_invEff[C_SZ];
__device__ float g_Spos[C_SZ];
__device__ float g_Sneg[C_SZ];
__device__ float g_Nsum[C_SZ];
__device__ unsigned g_done;

// ---------------- fast exp on FMA pipe ----------------
__device__ __forceinline__ float fexp(float x) {
    float t = x * 1.44269504088896341f;
    float fi = rintf(t);
    float f = t - fi;
    float p = 1.54035303933816e-4f;
    p = fmaf(p, f, 1.33335581467049e-3f);
    p = fmaf(p, f, 9.61812910762848e-3f);
    p = fmaf(p, f, 5.55041086648216e-2f);
    p = fmaf(p, f, 2.40226506959101e-1f);
    p = fmaf(p, f, 6.93147180559945e-1f);
    p = fmaf(p, f, 1.0f);
    int i = (int)fi;
    float s = __int_as_float((i + 127) << 23);
    return p * s;
}

// ---------------- fused prep kernel (no cross-block dependencies) ----------------
// blocks 0..2047   : proxy L2-norm + bf16 (8 rows per block, 1 warp/row)
// blocks 2048..2559: input f32->bf16 (1 float4/thread)
// blocks 2560..2623: per-class constants + accumulator zero
__global__ void __launch_bounds__(256) prepKernel(
    const float* __restrict__ inputs,
    const float* __restrict__ proxies, const float* __restrict__ effN,
    const float* __restrict__ ls)
{
    const int b = blockIdx.x;
    const int tid = threadIdx.x;
    if (b < 2048) {
        int row = b * 8 + (tid >> 5);
        int lane = tid & 31;
        const float4* p4 = (const float4*)(proxies + (size_t)row * E_SZ);
        float4 v[4];
        float s = 0.0f;
#pragma unroll
        for (int j = 0; j < 4; j++) {
            v[j] = __ldcs(&p4[lane + j * 32]);
            s += v[j].x * v[j].x + v[j].y * v[j].y + v[j].z * v[j].z + v[j].w * v[j].w;
        }
#pragma unroll
        for (int o = 16; o > 0; o >>= 1) s += __shfl_xor_sync(0xffffffffu, s, o);
        float rn = rsqrtf(s + 1e-12f);
        __nv_bfloat162* out = (__nv_bfloat162*)(g_proxyB + (size_t)row * E_SZ);
#pragma unroll
        for (int j = 0; j < 4; j++) {
            out[(lane + j * 32) * 2]     = __floats2bfloat162_rn(v[j].x * rn, v[j].y * rn);
            out[(lane + j * 32) * 2 + 1] = __floats2bfloat162_rn(v[j].z * rn, v[j].w * rn);
        }
    } else if (b < 2560) {
        int i = (b - 2048) * 256 + tid;          // over B*E/4 float4s
        float4 v = __ldcs(&((const float4*)inputs)[i]);
        __nv_bfloat162* o = (__nv_bfloat162*)g_inputB;
        o[i * 2]     = __floats2bfloat162_rn(v.x, v.y);
        o[i * 2 + 1] = __floats2bfloat162_rn(v.z, v.w);
    } else {
        int c = (b - 2560) * 256 + tid;
        float eff = effN[c], l = ls[c];
        float wb = 1.0f / (1.0f + log1pf(eff));
        float eta = (1.0f + (1.0f - l)) * wb + 0.1f;   // K=1, LAM=0.1
        g_outlier[c] = l - eta;
        g_invEff[c] = 1.0f / fmaxf(1.0f, eff);
        g_Spos[c] = 0.0f;
        g_Sneg[c] = 0.0f;
        g_Nsum[c] = 0.0f;
        if (b == 2560 && tid == 0) g_done = 0u;
    }
}

// ---------------- HMMA helpers ----------------
__device__ __forceinline__ uint32_t smem_u32(const void* p) {
    uint32_t a;
    asm("{ .reg .u64 t; cvta.to.shared.u64 t, %1; cvt.u32.u64 %0, t; }" : "=r"(a) : "l"(p));
    return a;
}
__device__ __forceinline__ void mma16816(float* d, const uint32_t* a, const uint32_t* b) {
    asm volatile(
        "mma.sync.aligned.m16n8k16.row.col.f32.bf16.bf16.f32 "
        "{%0,%1,%2,%3}, {%4,%5,%6,%7}, {%8,%9}, {%0,%1,%2,%3};\n"
        : "+f"(d[0]), "+f"(d[1]), "+f"(d[2]), "+f"(d[3])
        : "r"(a[0]), "r"(a[1]), "r"(a[2]), "r"(a[3]), "r"(b[0]), "r"(b[1]));
}
#define LDSM_X4(r, a) \
    asm volatile("ldmatrix.sync.aligned.m8n8.x4.shared.b16 {%0,%1,%2,%3}, [%4];" \
        : "=r"((r)[0]), "=r"((r)[1]), "=r"((r)[2]), "=r"((r)[3]) : "r"(a))

__device__ __forceinline__ void cpa16(uint32_t s, const void* g) {
    asm volatile("cp.async.cg.shared.global [%0], [%1], 16;" :: "r"(s), "l"(g));
}
#define CP_COMMIT() asm volatile("cp.async.commit_group;" ::: "memory")

// row r (128B rows), 16B granule g (0..7): xor swizzle
#define SWZ(r, g) ((r) * 128 + (((g) ^ ((r) & 7)) << 4))

// ---------------- persistent main HMMA kernel (+fused finalize) ----------------
// Tiles: 128x128, tile id t: cBase=(t&127)*128, mBase=(t>>7)*128; 1024 tiles.
// Grid = 296 persistent CTAs (2/SM). K chunks of 64 (8 per tile),
// 3-stage cp.async ring, prefetch distance 2, one syncthreads per chunk.
// Last CTA to finish computes the final scalar (histogram in stage smem).
#define GRID_MAIN 296
#define NTILES    1024

#define SM_TGT   0       // int [2][128]
#define SM_OUTL  1024    // float [2][128]
#define SM_IE    2048    // float [2][128]
#define SM_STG   3072    // 3 stages x (A 16KB + B 16KB)
#define SM_BYTES 101376

__global__ void __launch_bounds__(256, 2) mainHMMA(const int* __restrict__ targets,
                                                   float* __restrict__ gOut) {
    extern __shared__ __align__(1024) char sm[];
    __shared__ unsigned sdone;
    const uint32_t smb = smem_u32(sm);
    const int tid = threadIdx.x;
    const int lane = tid & 31;
    const int warp = tid >> 5;
    const int warpM = warp >> 2;   // 0..1 (64 rows each)
    const int warpN = warp & 3;    // 0..3 (32 cols each)
    const int bid = blockIdx.x;

    const int NT = (NTILES - bid + GRID_MAIN - 1) / GRID_MAIN;   // tiles this CTA
    const int NT8 = NT * 8;

    float acc[4][4][4];
#pragma unroll
    for (int i = 0; i < 4; i++)
#pragma unroll
        for (int j = 0; j < 4; j++)
#pragma unroll
            for (int e = 0; e < 4; e++) acc[i][j][e] = 0.0f;

    // prefetch global chunk gg (tile bid + (gg>>3)*296, k-chunk gg&7) into stage gg%3
#define PREFETCH(gg) do { \
        const int T_ = (gg) >> 3, k_ = (gg) & 7; \
        const int tt_ = bid + T_ * GRID_MAIN; \
        const int cB_ = (tt_ & 127) << 7, mB_ = (tt_ >> 7) << 7; \
        const int kOff_ = k_ * 64; \
        const uint32_t stg_ = smb + SM_STG + ((gg) % 3) * 32768; \
        _Pragma("unroll") \
        for (int i_ = 0; i_ < 4; i_++) { \
            int idx_ = tid + i_ * 256; int r_ = idx_ >> 3, q_ = idx_ & 7; \
            cpa16(stg_ + SWZ(r_, q_), \
                  g_inputB + (size_t)(mB_ + r_) * E_SZ + kOff_ + q_ * 8); \
        } \
        _Pragma("unroll") \
        for (int i_ = 0; i_ < 4; i_++) { \
            int idx_ = tid + i_ * 256; int r_ = idx_ >> 3, q_ = idx_ & 7; \
            cpa16(stg_ + 16384 + SWZ(r_, q_), \
                  g_proxyB + (size_t)(cB_ + r_) * E_SZ + kOff_ + q_ * 8); \
        } \
        if (k_ == 0) { \
            int par_ = (T_ & 1) << 9; \
            if (tid < 32)       cpa16(smb + SM_TGT  + par_ + tid * 16,        targets   + mB_ + tid * 4); \
            else if (tid < 64)  cpa16(smb + SM_OUTL + par_ + (tid - 32) * 16, g_outlier + cB_ + (tid - 32) * 4); \
            else if (tid < 96)  cpa16(smb + SM_IE   + par_ + (tid - 64) * 16, g_invEff  + cB_ + (tid - 64) * 4); \
        } \
        CP_COMMIT(); \
    } while (0)

    PREFETCH(0);
    if (NT8 > 1) PREFETCH(1);

#pragma unroll 1
    for (int g = 0; g < NT8; g++) {
        if (g < NT8 - 1) { asm volatile("cp.async.wait_group 1;" ::: "memory"); }
        else             { asm volatile("cp.async.wait_group 0;" ::: "memory"); }
        __syncthreads();
        if (g + 2 < NT8) PREFETCH(g + 2);

        const uint32_t aBase = smb + SM_STG + (g % 3) * 32768;
        const uint32_t bBase = aBase + 16384;
#pragma unroll
        for (int ks = 0; ks < 4; ks++) {
            uint32_t a[4][4], bfr[2][4];
#pragma unroll
            for (int mt = 0; mt < 4; mt++) {
                int r = warpM * 64 + mt * 16 + (lane & 15);
                int q = ks * 2 + (lane >> 4);
                LDSM_X4(a[mt], aBase + SWZ(r, q));
            }
#pragma unroll
            for (int np = 0; np < 2; np++) {
                int n = warpN * 32 + np * 16 + ((lane >> 4) << 3) + (lane & 7);
                int q = ks * 2 + ((lane >> 3) & 1);
                LDSM_X4(bfr[np], bBase + SWZ(n, q));
            }
#pragma unroll
            for (int mt = 0; mt < 4; mt++)
#pragma unroll
                for (int nt = 0; nt < 4; nt++)
                    mma16816(acc[mt][nt], a[mt], &bfr[nt >> 1][(nt & 1) * 2]);
        }

        if ((g & 7) == 7) {
            // ---- epilogue for tile T = g>>3 ----
            const int T = g >> 3;
            const int tt = bid + T * GRID_MAIN;
            const int cBase = (tt & 127) << 7;
            const int par = (T & 1) << 7;
            const int* shTgt = (const int*)(sm + SM_TGT) + par;
            const float* shOutl = (const float*)(sm + SM_OUTL) + par;
            const float* shIE = (const float*)(sm + SM_IE) + par;

            int tg[4][2];
#pragma unroll
            for (int mt = 0; mt < 4; mt++) {
                int rl = warpM * 64 + mt * 16 + (lane >> 2);
                tg[mt][0] = shTgt[rl];
                tg[mt][1] = shTgt[rl + 8];
            }
#pragma unroll
            for (int nt = 0; nt < 4; nt++) {
#pragma unroll
                for (int p = 0; p < 2; p++) {
                    int cc = warpN * 32 + nt * 8 + (lane & 3) * 2 + p;
                    float outl = shOutl[cc];
                    float ie = shIE[cc];
                    int clsG = cBase + cc;
                    float sP = 0.0f, sN = 0.0f, sV = 0.0f;
#pragma unroll
                    for (int mt = 0; mt < 4; mt++) {
#pragma unroll
                        for (int h = 0; h < 2; h++) {
                            float cv = acc[mt][nt][h * 2 + p];
                            if (tg[mt][h] == clsG) {
                                sP += fexp(32.0f * (0.1f - cv));
                            } else {
                                float nv = (cv < outl) ? ie : 1.0f;
                                sV += nv;
                                sN += fexp(32.0f * (cv + 0.1f) * nv);
                            }
                        }
                    }
#pragma unroll
                    for (int o = 4; o <= 16; o <<= 1) {
                        sP += __shfl_xor_sync(0xffffffffu, sP, o);
                        sN += __shfl_xor_sync(0xffffffffu, sN, o);
                        sV += __shfl_xor_sync(0xffffffffu, sV, o);
                    }
                    if ((lane >> 2) == 0) {
                        atomicAdd(&g_Spos[clsG], sP);
                        atomicAdd(&g_Sneg[clsG], sN);
                        atomicAdd(&g_Nsum[clsG], sV);
                    }
                }
            }
            // reset accumulators for next tile
#pragma unroll
            for (int i = 0; i < 4; i++)
#pragma unroll
                for (int j = 0; j < 4; j++)
#pragma unroll
                    for (int e = 0; e < 4; e++) acc[i][j][e] = 0.0f;
        }
    }

    // ---- last-CTA fused finalize ----
    __syncthreads();
    if (tid == 0) {
        __threadfence();
        sdone = atomicAdd(&g_done, 1u);
    }
    __syncthreads();
    if (sdone == GRID_MAIN - 1) {
        int* hist = (int*)(sm + SM_STG);                 // 64KB in stage area
        float* red = (float*)(sm + SM_STG + 65536);      // 4KB reduce area
        for (int c = tid; c < C_SZ; c += 256) hist[c] = 0;
        __syncthreads();
        for (int i = tid; i < B_SZ; i += 256) atomicAdd(&hist[targets[i]], 1);
        __syncthreads();
        float posT = 0.0f, negT = 0.0f, posW = 0.0f, negW = 0.0f;
        for (int c = tid; c < C_SZ; c += 256) {
            int cnt = hist[c];
            if (cnt > 0) { posW += 1.0f; posT += log1pf(__ldcg(&g_Spos[c])); }
            negT += log1pf(__ldcg(&g_Sneg[c]));
            int Ncnt = B_SZ - cnt;
            if (Ncnt > 0) negW += __ldcg(&g_Nsum[c]) / (float)Ncnt;
        }
        red[tid] = posT; red[256 + tid] = negT; red[512 + tid] = posW; red[768 + tid] = negW;
        __syncthreads();
        for (int s = 128; s > 0; s >>= 1) {
            if (tid < s) {
                red[tid] += red[tid + s];
                red[256 + tid] += red[256 + tid + s];
                red[512 + tid] += red[512 + tid + s];
                red[768 + tid] += red[768 + tid + s];
            }
            __syncthreads();
        }
        if (tid == 0) gOut[0] = red[0] / red[512] + red[256] / red[768];
    }
}

// ---------------- launch ----------------
extern "C" void kernel_launch(void* const* d_in, const int* in_sizes, int n_in,
                              void* d_out, int out_size) {
    const float* inputs  = (const float*)d_in[0];   // [B,E] f32
    const int*   targets = (const int*)d_in[1];     // [B]   i32
    const float* proxies = (const float*)d_in[2];   // [C,E] f32
    const float* effN    = (const float*)d_in[3];   // [C]
    const float* ls      = (const float*)d_in[4];   // [C]
    float* out = (float*)d_out;

    cudaFuncSetAttribute(mainHMMA, cudaFuncAttributeMaxDynamicSharedMemorySize, SM_BYTES);

    prepKernel<<<2624, 256>>>(inputs, proxies, effN, ls);
    mainHMMA<<<GRID_MAIN, 256, SM_BYTES>>>(targets, out);
}

// round 10
// speedup vs baseline: 1.8878x; 1.4868x over previous
#include <cuda_runtime.h>
#include <cuda_bf16.h>
#include <cstdint>

#define B_SZ 1024
#define E_SZ 512
#define C_SZ 16384

// ---------------- scratch (static device memory; no runtime alloc) ----------------
__device__ __nv_bfloat16 g_proxyB[C_SZ * E_SZ];   // normalized proxies, bf16
__device__ __nv_bfloat16 g_inputB[B_SZ * E_SZ];   // inputs, bf16
__device__ float g_outlier[C_SZ];
__device__ float g_invEff[C_SZ];
__device__ float g_Spos[C_SZ];
__device__ float g_Sneg[C_SZ];
__device__ float g_Nsum[C_SZ];

// ---------------- fast exp on FMA pipe ----------------
__device__ __forceinline__ float fexp(float x) {
    float t = x * 1.44269504088896341f;
    float fi = rintf(t);
    float f = t - fi;
    float p = 1.54035303933816e-4f;
    p = fmaf(p, f, 1.33335581467049e-3f);
    p = fmaf(p, f, 9.61812910762848e-3f);
    p = fmaf(p, f, 5.55041086648216e-2f);
    p = fmaf(p, f, 2.40226506959101e-1f);
    p = fmaf(p, f, 6.93147180559945e-1f);
    p = fmaf(p, f, 1.0f);
    int i = (int)fi;
    float s = __int_as_float((i + 127) << 23);
    return p * s;
}

// ---------------- fused prep kernel (no cross-block dependencies) ----------------
__global__ void __launch_bounds__(256) prepKernel(
    const float* __restrict__ inputs,
    const float* __restrict__ proxies, const float* __restrict__ effN,
    const float* __restrict__ ls)
{
    const int b = blockIdx.x;
    const int tid = threadIdx.x;
    if (b < 2048) {
        int row = b * 8 + (tid >> 5);
        int lane = tid & 31;
        const float4* p4 = (const float4*)(proxies + (size_t)row * E_SZ);
        float4 v[4];
        float s = 0.0f;
#pragma unroll
        for (int j = 0; j < 4; j++) {
            v[j] = p4[lane + j * 32];
            s += v[j].x * v[j].x + v[j].y * v[j].y + v[j].z * v[j].z + v[j].w * v[j].w;
        }
#pragma unroll
        for (int o = 16; o > 0; o >>= 1) s += __shfl_xor_sync(0xffffffffu, s, o);
        float rn = rsqrtf(s + 1e-12f);
        __nv_bfloat162* out = (__nv_bfloat162*)(g_proxyB + (size_t)row * E_SZ);
#pragma unroll
        for (int j = 0; j < 4; j++) {
            out[(lane + j * 32) * 2]     = __floats2bfloat162_rn(v[j].x * rn, v[j].y * rn);
            out[(lane + j * 32) * 2 + 1] = __floats2bfloat162_rn(v[j].z * rn, v[j].w * rn);
        }
    } else if (b < 2560) {
        int i = (b - 2048) * 256 + tid;          // over B*E/4 float4s
        float4 v = ((const float4*)inputs)[i];
        __nv_bfloat162* o = (__nv_bfloat162*)g_inputB;
        o[i * 2]     = __floats2bfloat162_rn(v.x, v.y);
        o[i * 2 + 1] = __floats2bfloat162_rn(v.z, v.w);
    } else {
        int c = (b - 2560) * 256 + tid;
        float eff = effN[c], l = ls[c];
        float wb = 1.0f / (1.0f + log1pf(eff));
        float eta = (1.0f + (1.0f - l)) * wb + 0.1f;   // K=1, LAM=0.1
        g_outlier[c] = l - eta;
        g_invEff[c] = 1.0f / fmaxf(1.0f, eff);
        g_Spos[c] = 0.0f;
        g_Sneg[c] = 0.0f;
        g_Nsum[c] = 0.0f;
    }
}

// ---------------- HMMA helpers ----------------
__device__ __forceinline__ uint32_t smem_u32(const void* p) {
    uint32_t a;
    asm("{ .reg .u64 t; cvta.to.shared.u64 t, %1; cvt.u32.u64 %0, t; }" : "=r"(a) : "l"(p));
    return a;
}
__device__ __forceinline__ void mma16816(float* d, const uint32_t* a, const uint32_t* b) {
    asm volatile(
        "mma.sync.aligned.m16n8k16.row.col.f32.bf16.bf16.f32 "
        "{%0,%1,%2,%3}, {%4,%5,%6,%7}, {%8,%9}, {%0,%1,%2,%3};\n"
        : "+f"(d[0]), "+f"(d[1]), "+f"(d[2]), "+f"(d[3])
        : "r"(a[0]), "r"(a[1]), "r"(a[2]), "r"(a[3]), "r"(b[0]), "r"(b[1]));
}
#define LDSM_X4(r, a) \
    asm volatile("ldmatrix.sync.aligned.m8n8.x4.shared.b16 {%0,%1,%2,%3}, [%4];" \
        : "=r"((r)[0]), "=r"((r)[1]), "=r"((r)[2]), "=r"((r)[3]) : "r"(a))

__device__ __forceinline__ void cpa16(uint32_t s, const void* g) {
    asm volatile("cp.async.cg.shared.global [%0], [%1], 16;" :: "r"(s), "l"(g));
}
#define CP_COMMIT() asm volatile("cp.async.commit_group;" ::: "memory")

// row r (128B rows), 16B granule g (0..7): xor swizzle
#define SWZ(r, g) ((r) * 128 + (((g) ^ ((r) & 7)) << 4))

// ---------------- persistent main HMMA kernel ----------------
// Tiles: 128x128, tile id t: cBase=(t&127)*128, mBase=(t>>7)*128; 1024 tiles.
// Grid = 296 persistent CTAs (2/SM), 512 threads = 16 warps, warp grid
// 4(M) x 4(N): warp tile 32x32 (acc = 32 regs). K chunks of 64 (8/tile),
// 3-stage cp.async ring, prefetch distance 2, one syncthreads per chunk.
#define GRID_MAIN 296
#define NTILES    1024

#define SM_TGT   0       // int [2][128]
#define SM_OUTL  1024    // float [2][128]
#define SM_IE    2048    // float [2][128]
#define SM_STG   3072    // 3 stages x (A 16KB + B 16KB)
#define SM_BYTES 101376

__global__ void __launch_bounds__(512, 2) mainHMMA(const int* __restrict__ targets) {
    extern __shared__ __align__(1024) char sm[];
    const uint32_t smb = smem_u32(sm);
    const int tid = threadIdx.x;
    const int lane = tid & 31;
    const int warp = tid >> 5;
    const int warpM = warp >> 2;   // 0..3 (32 rows each)
    const int warpN = warp & 3;    // 0..3 (32 cols each)
    const int bid = blockIdx.x;

    const int NT = (NTILES - bid + GRID_MAIN - 1) / GRID_MAIN;   // tiles this CTA
    const int NT8 = NT * 8;

    float acc[2][4][4];
#pragma unroll
    for (int i = 0; i < 2; i++)
#pragma unroll
        for (int j = 0; j < 4; j++)
#pragma unroll
            for (int e = 0; e < 4; e++) acc[i][j][e] = 0.0f;

    // prefetch global chunk gg (tile bid + (gg>>3)*296, k-chunk gg&7) into stage gg%3
#define PREFETCH(gg) do { \
        const int T_ = (gg) >> 3, k_ = (gg) & 7; \
        const int tt_ = bid + T_ * GRID_MAIN; \
        const int cB_ = (tt_ & 127) << 7, mB_ = (tt_ >> 7) << 7; \
        const int kOff_ = k_ * 64; \
        const uint32_t stg_ = smb + SM_STG + ((gg) % 3) * 32768; \
        _Pragma("unroll") \
        for (int i_ = 0; i_ < 2; i_++) { \
            int idx_ = tid + i_ * 512; int r_ = idx_ >> 3, q_ = idx_ & 7; \
            cpa16(stg_ + SWZ(r_, q_), \
                  g_inputB + (size_t)(mB_ + r_) * E_SZ + kOff_ + q_ * 8); \
        } \
        _Pragma("unroll") \
        for (int i_ = 0; i_ < 2; i_++) { \
            int idx_ = tid + i_ * 512; int r_ = idx_ >> 3, q_ = idx_ & 7; \
            cpa16(stg_ + 16384 + SWZ(r_, q_), \
                  g_proxyB + (size_t)(cB_ + r_) * E_SZ + kOff_ + q_ * 8); \
        } \
        if (k_ == 0) { \
            int par_ = (T_ & 1) << 9; \
            if (tid < 32)       cpa16(smb + SM_TGT  + par_ + tid * 16,        targets   + mB_ + tid * 4); \
            else if (tid < 64)  cpa16(smb + SM_OUTL + par_ + (tid - 32) * 16, g_outlier + cB_ + (tid - 32) * 4); \
            else if (tid < 96)  cpa16(smb + SM_IE   + par_ + (tid - 64) * 16, g_invEff  + cB_ + (tid - 64) * 4); \
        } \
        CP_COMMIT(); \
    } while (0)

    PREFETCH(0);
    if (NT8 > 1) PREFETCH(1);

#pragma unroll 1
    for (int g = 0; g < NT8; g++) {
        if (g < NT8 - 1) { asm volatile("cp.async.wait_group 1;" ::: "memory"); }
        else             { asm volatile("cp.async.wait_group 0;" ::: "memory"); }
        __syncthreads();
        if (g + 2 < NT8) PREFETCH(g + 2);

        const uint32_t aBase = smb + SM_STG + (g % 3) * 32768;
        const uint32_t bBase = aBase + 16384;
#pragma unroll
        for (int ks = 0; ks < 4; ks++) {
            uint32_t a[2][4], bfr[2][4];
#pragma unroll
            for (int mt = 0; mt < 2; mt++) {
                int r = warpM * 32 + mt * 16 + (lane & 15);
                int q = ks * 2 + (lane >> 4);
                LDSM_X4(a[mt], aBase + SWZ(r, q));
            }
#pragma unroll
            for (int np = 0; np < 2; np++) {
                int n = warpN * 32 + np * 16 + ((lane >> 4) << 3) + (lane & 7);
                int q = ks * 2 + ((lane >> 3) & 1);
                LDSM_X4(bfr[np], bBase + SWZ(n, q));
            }
#pragma unroll
            for (int mt = 0; mt < 2; mt++)
#pragma unroll
                for (int nt = 0; nt < 4; nt++)
                    mma16816(acc[mt][nt], a[mt], &bfr[nt >> 1][(nt & 1) * 2]);
        }

        if ((g & 7) == 7) {
            // ---- epilogue for tile T = g>>3 ----
            const int T = g >> 3;
            const int tt = bid + T * GRID_MAIN;
            const int cBase = (tt & 127) << 7;
            const int par = (T & 1) << 7;
            const int* shTgt = (const int*)(sm + SM_TGT) + par;
            const float* shOutl = (const float*)(sm + SM_OUTL) + par;
            const float* shIE = (const float*)(sm + SM_IE) + par;

            int tg[2][2];
#pragma unroll
            for (int mt = 0; mt < 2; mt++) {
                int rl = warpM * 32 + mt * 16 + (lane >> 2);
                tg[mt][0] = shTgt[rl];
                tg[mt][1] = shTgt[rl + 8];
            }
#pragma unroll
            for (int nt = 0; nt < 4; nt++) {
#pragma unroll
                for (int p = 0; p < 2; p++) {
                    int cc = warpN * 32 + nt * 8 + (lane & 3) * 2 + p;
                    float outl = shOutl[cc];
                    float ie = shIE[cc];
                    int clsG = cBase + cc;
                    float sP = 0.0f, sN = 0.0f, sV = 0.0f;
#pragma unroll
                    for (int mt = 0; mt < 2; mt++) {
#pragma unroll
                        for (int h = 0; h < 2; h++) {
                            float cv = acc[mt][nt][h * 2 + p];
                            if (tg[mt][h] == clsG) {
                                sP += fexp(32.0f * (0.1f - cv));
                            } else {
                                float nv = (cv < outl) ? ie : 1.0f;
                                sV += nv;
                                sN += fexp(32.0f * (cv + 0.1f) * nv);
                            }
                        }
                    }
#pragma unroll
                    for (int o = 4; o <= 16; o <<= 1) {
                        sP += __shfl_xor_sync(0xffffffffu, sP, o);
                        sN += __shfl_xor_sync(0xffffffffu, sN, o);
                        sV += __shfl_xor_sync(0xffffffffu, sV, o);
                    }
                    if ((lane >> 2) == 0) {
                        atomicAdd(&g_Spos[clsG], sP);
                        atomicAdd(&g_Sneg[clsG], sN);
                        atomicAdd(&g_Nsum[clsG], sV);
                    }
                }
            }
            // reset accumulators for next tile
#pragma unroll
            for (int i = 0; i < 2; i++)
#pragma unroll
                for (int j = 0; j < 4; j++)
#pragma unroll
                    for (int e = 0; e < 4; e++) acc[i][j][e] = 0.0f;
        }
    }
}

// ---------------- finalize (single block: race-free shared histogram) ----------------
#define FIN_SMEM (C_SZ * 4)
__global__ void __launch_bounds__(1024) finalizeKernel(const int* __restrict__ targets,
                                                       float* __restrict__ out) {
    extern __shared__ int scnt[];
    __shared__ float smr[4][1024];
    int tid = threadIdx.x;
    for (int c = tid; c < C_SZ; c += 1024) scnt[c] = 0;
    __syncthreads();
    atomicAdd(&scnt[targets[tid]], 1);   // blockDim == B_SZ == 1024
    __syncthreads();

    float posT = 0.0f, negT = 0.0f, posW = 0.0f, negW = 0.0f;
    for (int c = tid; c < C_SZ; c += 1024) {
        int cnt = scnt[c];
        if (cnt > 0) { posW += 1.0f; posT += log1pf(g_Spos[c]); }
        negT += log1pf(g_Sneg[c]);
        int Ncnt = B_SZ - cnt;
        float nm = g_Nsum[c] / fmaxf((float)Ncnt, 1.0f);
        if (Ncnt > 0) negW += nm;
    }
    smr[0][tid] = posT; smr[1][tid] = negT; smr[2][tid] = posW; smr[3][tid] = negW;
    __syncthreads();
    for (int s = 512; s > 0; s >>= 1) {
        if (tid < s) {
#pragma unroll
            for (int j = 0; j < 4; j++) smr[j][tid] += smr[j][tid + s];
        }
        __syncthreads();
    }
    if (tid == 0) out[0] = smr[0][0] / smr[2][0] + smr[1][0] / smr[3][0];
}

// ---------------- launch ----------------
extern "C" void kernel_launch(void* const* d_in, const int* in_sizes, int n_in,
                              void* d_out, int out_size) {
    const float* inputs  = (const float*)d_in[0];   // [B,E] f32
    const int*   targets = (const int*)d_in[1];     // [B]   i32
    const float* proxies = (const float*)d_in[2];   // [C,E] f32
    const float* effN    = (const float*)d_in[3];   // [C]
    const float* ls      = (const float*)d_in[4];   // [C]
    float* out = (float*)d_out;

    cudaFuncSetAttribute(mainHMMA, cudaFuncAttributeMaxDynamicSharedMemorySize, SM_BYTES);
    cudaFuncSetAttribute(finalizeKernel, cudaFuncAttributeMaxDynamicSharedMemorySize, FIN_SMEM);

    prepKernel<<<2624, 256>>>(inputs, proxies, effN, ls);
    mainHMMA<<<GRID_MAIN, 512, SM_BYTES>>>(targets);
    finalizeKernel<<<1, 1024, FIN_SMEM>>>(targets, out);
}

// round 11
// speedup vs baseline: 2.0582x; 1.0903x over previous
#include <cuda_runtime.h>
#include <cuda_bf16.h>
#include <cstdint>

#define B_SZ 1024
#define E_SZ 512
#define C_SZ 16384

// ---------------- scratch (static device memory; no runtime alloc) ----------------
__device__ __nv_bfloat16 g_proxyB[C_SZ * E_SZ];   // normalized proxies, bf16
__device__ __nv_bfloat16 g_inputB[B_SZ * E_SZ];   // inputs, bf16
__device__ float g_outlier[C_SZ];
__device__ float g_invEff[C_SZ];
__device__ float g_Spos[C_SZ];
__device__ float g_Sneg[C_SZ];
__device__ float g_Nsum[C_SZ];

// exp(x) = 2^(x*log2e) via MUFU.EX2 — 1 issue slot on the (idle) MUFU pipe
__device__ __forceinline__ float ex2(float x) {
    float r;
    asm("ex2.approx.f32 %0, %1;" : "=f"(r) : "f"(x));
    return r;
}
#define A_L2E 46.166241308446828f   // 32 * log2(e)

// ---------------- fused prep kernel (no cross-block dependencies) ----------------
__global__ void __launch_bounds__(256) prepKernel(
    const float* __restrict__ inputs,
    const float* __restrict__ proxies, const float* __restrict__ effN,
    const float* __restrict__ ls)
{
    const int b = blockIdx.x;
    const int tid = threadIdx.x;
    if (b < 2048) {
        int row = b * 8 + (tid >> 5);
        int lane = tid & 31;
        const float4* p4 = (const float4*)(proxies + (size_t)row * E_SZ);
        float4 v[4];
        float s = 0.0f;
#pragma unroll
        for (int j = 0; j < 4; j++) {
            v[j] = p4[lane + j * 32];
            s += v[j].x * v[j].x + v[j].y * v[j].y + v[j].z * v[j].z + v[j].w * v[j].w;
        }
#pragma unroll
        for (int o = 16; o > 0; o >>= 1) s += __shfl_xor_sync(0xffffffffu, s, o);
        float rn = rsqrtf(s + 1e-12f);
        __nv_bfloat162* out = (__nv_bfloat162*)(g_proxyB + (size_t)row * E_SZ);
#pragma unroll
        for (int j = 0; j < 4; j++) {
            out[(lane + j * 32) * 2]     = __floats2bfloat162_rn(v[j].x * rn, v[j].y * rn);
            out[(lane + j * 32) * 2 + 1] = __floats2bfloat162_rn(v[j].z * rn, v[j].w * rn);
        }
    } else if (b < 2560) {
        int i = (b - 2048) * 256 + tid;          // over B*E/4 float4s
        float4 v = ((const float4*)inputs)[i];
        __nv_bfloat162* o = (__nv_bfloat162*)g_inputB;
        o[i * 2]     = __floats2bfloat162_rn(v.x, v.y);
        o[i * 2 + 1] = __floats2bfloat162_rn(v.z, v.w);
    } else {
        int c = (b - 2560) * 256 + tid;
        float eff = effN[c], l = ls[c];
        float wb = 1.0f / (1.0f + log1pf(eff));
        float eta = (1.0f + (1.0f - l)) * wb + 0.1f;   // K=1, LAM=0.1
        g_outlier[c] = l - eta;
        g_invEff[c] = 1.0f / fmaxf(1.0f, eff);
        g_Spos[c] = 0.0f;
        g_Sneg[c] = 0.0f;
        g_Nsum[c] = 0.0f;
    }
}

// ---------------- HMMA helpers ----------------
__device__ __forceinline__ uint32_t smem_u32(const void* p) {
    uint32_t a;
    asm("{ .reg .u64 t; cvta.to.shared.u64 t, %1; cvt.u32.u64 %0, t; }" : "=r"(a) : "l"(p));
    return a;
}
__device__ __forceinline__ void mma16816(float* d, const uint32_t* a, const uint32_t* b) {
    asm volatile(
        "mma.sync.aligned.m16n8k16.row.col.f32.bf16.bf16.f32 "
        "{%0,%1,%2,%3}, {%4,%5,%6,%7}, {%8,%9}, {%0,%1,%2,%3};\n"
        : "+f"(d[0]), "+f"(d[1]), "+f"(d[2]), "+f"(d[3])
        : "r"(a[0]), "r"(a[1]), "r"(a[2]), "r"(a[3]), "r"(b[0]), "r"(b[1]));
}
#define LDSM_X4(r, a) \
    asm volatile("ldmatrix.sync.aligned.m8n8.x4.shared.b16 {%0,%1,%2,%3}, [%4];" \
        : "=r"((r)[0]), "=r"((r)[1]), "=r"((r)[2]), "=r"((r)[3]) : "r"(a))

__device__ __forceinline__ void cpa16(uint32_t s, const void* g) {
    asm volatile("cp.async.cg.shared.global [%0], [%1], 16;" :: "r"(s), "l"(g));
}
#define CP_COMMIT() asm volatile("cp.async.commit_group;" ::: "memory")

// row r (128B rows), 16B granule g (0..7): xor swizzle
#define SWZ(r, g) ((r) * 128 + (((g) ^ ((r) & 7)) << 4))

// ---------------- persistent main HMMA kernel ----------------
// Tiles: 128x128, tile id t: cBase=(t&127)*128, mBase=(t>>7)*128; 1024 tiles.
// Grid = 296 persistent CTAs (2/SM), 256 threads = 8 warps, warp grid
// 2(M) x 4(N): warp tile 64x32. K chunks of 64 (8/tile), 3-stage cp.async
// ring, prefetch distance 2, one syncthreads per chunk.
#define GRID_MAIN 296
#define NTILES    1024

#define SM_TGT   0       // int [2][128]
#define SM_OUTL  1024    // float [2][128]
#define SM_IE    2048    // float [2][128]
#define SM_STG   3072    // 3 stages x (A 16KB + B 16KB)
#define SM_BYTES 101376

__global__ void __launch_bounds__(256, 2) mainHMMA(const int* __restrict__ targets) {
    extern __shared__ __align__(1024) char sm[];
    const uint32_t smb = smem_u32(sm);
    const int tid = threadIdx.x;
    const int lane = tid & 31;
    const int warp = tid >> 5;
    const int warpM = warp >> 2;   // 0..1 (64 rows each)
    const int warpN = warp & 3;    // 0..3 (32 cols each)
    const int bid = blockIdx.x;

    const int NT = (NTILES - bid + GRID_MAIN - 1) / GRID_MAIN;   // tiles this CTA
    const int NT8 = NT * 8;

    float acc[4][4][4];
#pragma unroll
    for (int i = 0; i < 4; i++)
#pragma unroll
        for (int j = 0; j < 4; j++)
#pragma unroll
            for (int e = 0; e < 4; e++) acc[i][j][e] = 0.0f;

    // prefetch global chunk gg (tile bid + (gg>>3)*296, k-chunk gg&7) into stage gg%3
#define PREFETCH(gg) do { \
        const int T_ = (gg) >> 3, k_ = (gg) & 7; \
        const int tt_ = bid + T_ * GRID_MAIN; \
        const int cB_ = (tt_ & 127) << 7, mB_ = (tt_ >> 7) << 7; \
        const int kOff_ = k_ * 64; \
        const uint32_t stg_ = smb + SM_STG + ((gg) % 3) * 32768; \
        _Pragma("unroll") \
        for (int i_ = 0; i_ < 4; i_++) { \
            int idx_ = tid + i_ * 256; int r_ = idx_ >> 3, q_ = idx_ & 7; \
            cpa16(stg_ + SWZ(r_, q_), \
                  g_inputB + (size_t)(mB_ + r_) * E_SZ + kOff_ + q_ * 8); \
        } \
        _Pragma("unroll") \
        for (int i_ = 0; i_ < 4; i_++) { \
            int idx_ = tid + i_ * 256; int r_ = idx_ >> 3, q_ = idx_ & 7; \
            cpa16(stg_ + 16384 + SWZ(r_, q_), \
                  g_proxyB + (size_t)(cB_ + r_) * E_SZ + kOff_ + q_ * 8); \
        } \
        if (k_ == 0) { \
            int par_ = (T_ & 1) << 9; \
            if (tid < 32)       cpa16(smb + SM_TGT  + par_ + tid * 16,        targets   + mB_ + tid * 4); \
            else if (tid < 64)  cpa16(smb + SM_OUTL + par_ + (tid - 32) * 16, g_outlier + cB_ + (tid - 32) * 4); \
            else if (tid < 96)  cpa16(smb + SM_IE   + par_ + (tid - 64) * 16, g_invEff  + cB_ + (tid - 64) * 4); \
        } \
        CP_COMMIT(); \
    } while (0)

    PREFETCH(0);
    if (NT8 > 1) PREFETCH(1);

#pragma unroll 1
    for (int g = 0; g < NT8; g++) {
        if (g < NT8 - 1) { asm volatile("cp.async.wait_group 1;" ::: "memory"); }
        else             { asm volatile("cp.async.wait_group 0;" ::: "memory"); }
        __syncthreads();
        if (g + 2 < NT8) PREFETCH(g + 2);

        const uint32_t aBase = smb + SM_STG + (g % 3) * 32768;
        const uint32_t bBase = aBase + 16384;
#pragma unroll
        for (int ks = 0; ks < 4; ks++) {
            uint32_t a[4][4], bfr[2][4];
#pragma unroll
            for (int mt = 0; mt < 4; mt++) {
                int r = warpM * 64 + mt * 16 + (lane & 15);
                int q = ks * 2 + (lane >> 4);
                LDSM_X4(a[mt], aBase + SWZ(r, q));
            }
#pragma unroll
            for (int np = 0; np < 2; np++) {
                int n = warpN * 32 + np * 16 + ((lane >> 4) << 3) + (lane & 7);
                int q = ks * 2 + ((lane >> 3) & 1);
                LDSM_X4(bfr[np], bBase + SWZ(n, q));
            }
#pragma unroll
            for (int mt = 0; mt < 4; mt++)
#pragma unroll
                for (int nt = 0; nt < 4; nt++)
                    mma16816(acc[mt][nt], a[mt], &bfr[nt >> 1][(nt & 1) * 2]);
        }

        if ((g & 7) == 7) {
            // ---- epilogue for tile T = g>>3 ----
            const int T = g >> 3;
            const int tt = bid + T * GRID_MAIN;
            const int cBase = (tt & 127) << 7;
            const int par = (T & 1) << 7;
            const int* shTgt = (const int*)(sm + SM_TGT) + par;
            const float* shOutl = (const float*)(sm + SM_OUTL) + par;
            const float* shIE = (const float*)(sm + SM_IE) + par;

            int tg[4][2];
#pragma unroll
            for (int mt = 0; mt < 4; mt++) {
                int rl = warpM * 64 + mt * 16 + (lane >> 2);
                tg[mt][0] = shTgt[rl];
                tg[mt][1] = shTgt[rl + 8];
            }
#pragma unroll
            for (int nt = 0; nt < 4; nt++) {
#pragma unroll
                for (int p = 0; p < 2; p++) {
                    int cc = warpN * 32 + nt * 8 + (lane & 3) * 2 + p;
                    float outl = shOutl[cc];
                    float ie = shIE[cc];
                    // fold 32*log2e and the 0.1 shift into per-column FMA constants:
                    // neg arg = A_L2E*nv*cv + A_L2E*nv*0.1
                    float s1 = A_L2E * ie,  c1 = s1 * 0.1f;   // nv = ie
                    float s0 = A_L2E,       c0 = A_L2E * 0.1f; // nv = 1
                    int clsG = cBase + cc;
                    float sP = 0.0f, sN = 0.0f, sV = 0.0f;
#pragma unroll
                    for (int mt = 0; mt < 4; mt++) {
#pragma unroll
                        for (int h = 0; h < 2; h++) {
                            float cv = acc[mt][nt][h * 2 + p];
                            if (tg[mt][h] == clsG) {
                                sP += ex2(fmaf(-A_L2E, cv, c0));   // 32*(0.1-cv)*log2e
                            } else {
                                bool low = (cv < outl);
                                sV += low ? ie : 1.0f;
                                float xr = low ? fmaf(s1, cv, c1) : fmaf(s0, cv, c0);
                                sN += ex2(xr);
                            }
                        }
                    }
#pragma unroll
                    for (int o = 4; o <= 16; o <<= 1) {
                        sP += __shfl_xor_sync(0xffffffffu, sP, o);
                        sN += __shfl_xor_sync(0xffffffffu, sN, o);
                        sV += __shfl_xor_sync(0xffffffffu, sV, o);
                    }
                    if ((lane >> 2) == 0) {
                        atomicAdd(&g_Spos[clsG], sP);
                        atomicAdd(&g_Sneg[clsG], sN);
                        atomicAdd(&g_Nsum[clsG], sV);
                    }
                }
            }
            // reset accumulators for next tile
#pragma unroll
            for (int i = 0; i < 4; i++)
#pragma unroll
                for (int j = 0; j < 4; j++)
#pragma unroll
                    for (int e = 0; e < 4; e++) acc[i][j][e] = 0.0f;
        }
    }
}

// ---------------- finalize (single block: race-free shared histogram) ----------------
#define FIN_SMEM (C_SZ * 4)
__global__ void __launch_bounds__(1024) finalizeKernel(const int* __restrict__ targets,
                                                       float* __restrict__ out) {
    extern __shared__ int scnt[];
    __shared__ float smr[4][1024];
    int tid = threadIdx.x;
    for (int c = tid; c < C_SZ; c += 1024) scnt[c] = 0;
    __syncthreads();
    atomicAdd(&scnt[targets[tid]], 1);   // blockDim == B_SZ == 1024
    __syncthreads();

    float posT = 0.0f, negT = 0.0f, posW = 0.0f, negW = 0.0f;
    for (int c = tid; c < C_SZ; c += 1024) {
        int cnt = scnt[c];
        if (cnt > 0) { posW += 1.0f; posT += log1pf(g_Spos[c]); }
        negT += log1pf(g_Sneg[c]);
        int Ncnt = B_SZ - cnt;
        float nm = g_Nsum[c] / fmaxf((float)Ncnt, 1.0f);
        if (Ncnt > 0) negW += nm;
    }
    smr[0][tid] = posT; smr[1][tid] = negT; smr[2][tid] = posW; smr[3][tid] = negW;
    __syncthreads();
    for (int s = 512; s > 0; s >>= 1) {
        if (tid < s) {
#pragma unroll
            for (int j = 0; j < 4; j++) smr[j][tid] += smr[j][tid + s];
        }
        __syncthreads();
    }
    if (tid == 0) out[0] = smr[0][0] / smr[2][0] + smr[1][0] / smr[3][0];
}

// ---------------- launch ----------------
extern "C" void kernel_launch(void* const* d_in, const int* in_sizes, int n_in,
                              void* d_out, int out_size) {
    const float* inputs  = (const float*)d_in[0];   // [B,E] f32
    const int*   targets = (const int*)d_in[1];     // [B]   i32
    const float* proxies = (const float*)d_in[2];   // [C,E] f32
    const float* effN    = (const float*)d_in[3];   // [C]
    const float* ls      = (const float*)d_in[4];   // [C]
    float* out = (float*)d_out;

    cudaFuncSetAttribute(mainHMMA, cudaFuncAttributeMaxDynamicSharedMemorySize, SM_BYTES);
    cudaFuncSetAttribute(finalizeKernel, cudaFuncAttributeMaxDynamicSharedMemorySize, FIN_SMEM);

    prepKernel<<<2624, 256>>>(inputs, proxies, effN, ls);
    mainHMMA<<<GRID_MAIN, 256, SM_BYTES>>>(targets);
    finalizeKernel<<<1, 1024, FIN_SMEM>>>(targets, out);
}

// round 12
// speedup vs baseline: 2.2254x; 1.0812x over previous
#include <cuda_runtime.h>
#include <cuda_bf16.h>
#include <cstdint>

#define B_SZ 1024
#define E_SZ 512
#define C_SZ 16384

// ---------------- scratch (static device memory; no runtime alloc) ----------------
__device__ __nv_bfloat16 g_proxyB[C_SZ * E_SZ];   // normalized proxies, bf16
__device__ __nv_bfloat16 g_inputB[B_SZ * E_SZ];   // inputs, bf16
__device__ float g_outlier[C_SZ];
__device__ float g_invEff[C_SZ];
__device__ float g_Spos[C_SZ];
__device__ float g_Sneg[C_SZ];
__device__ float g_Nsum[C_SZ];
__device__ unsigned g_tileCtr;

// exp(32*(...)) via MUFU.EX2 — 1 issue slot on the (idle) MUFU pipe
__device__ __forceinline__ float ex2(float x) {
    float r;
    asm("ex2.approx.f32 %0, %1;" : "=f"(r) : "f"(x));
    return r;
}
#define A_L2E 46.166241308446828f   // 32 * log2(e)

// log1p via MUFU.LG2 (abs err ~2.4e-7, fine vs 1e-3 threshold)
__device__ __forceinline__ float flog1p(float x) {
    float r;
    asm("lg2.approx.f32 %0, %1;" : "=f"(r) : "f"(1.0f + x));
    return 0.693147180559945f * r;
}

#define GRID_MAIN 296
#define NTILES    1024

// ---------------- fused prep kernel (no cross-block dependencies) ----------------
__global__ void __launch_bounds__(256) prepKernel(
    const float* __restrict__ inputs,
    const float* __restrict__ proxies, const float* __restrict__ effN,
    const float* __restrict__ ls)
{
    const int b = blockIdx.x;
    const int tid = threadIdx.x;
    if (b < 2048) {
        int row = b * 8 + (tid >> 5);
        int lane = tid & 31;
        const float4* p4 = (const float4*)(proxies + (size_t)row * E_SZ);
        float4 v[4];
        float s = 0.0f;
#pragma unroll
        for (int j = 0; j < 4; j++) {
            v[j] = p4[lane + j * 32];
            s += v[j].x * v[j].x + v[j].y * v[j].y + v[j].z * v[j].z + v[j].w * v[j].w;
        }
#pragma unroll
        for (int o = 16; o > 0; o >>= 1) s += __shfl_xor_sync(0xffffffffu, s, o);
        float rn = rsqrtf(s + 1e-12f);
        uint2* out = (uint2*)(g_proxyB + (size_t)row * E_SZ);
#pragma unroll
        for (int j = 0; j < 4; j++) {
            __nv_bfloat162 lo = __floats2bfloat162_rn(v[j].x * rn, v[j].y * rn);
            __nv_bfloat162 hi = __floats2bfloat162_rn(v[j].z * rn, v[j].w * rn);
            uint2 pk;
            pk.x = *(uint32_t*)&lo;
            pk.y = *(uint32_t*)&hi;
            out[lane + j * 32] = pk;
        }
    } else if (b < 2560) {
        int i = (b - 2048) * 256 + tid;          // over B*E/4 float4s
        float4 v = ((const float4*)inputs)[i];
        __nv_bfloat162 lo = __floats2bfloat162_rn(v.x, v.y);
        __nv_bfloat162 hi = __floats2bfloat162_rn(v.z, v.w);
        uint2 pk;
        pk.x = *(uint32_t*)&lo;
        pk.y = *(uint32_t*)&hi;
        ((uint2*)g_inputB)[i] = pk;
    } else {
        int c = (b - 2560) * 256 + tid;
        float eff = effN[c], l = ls[c];
        float wb = 1.0f / (1.0f + log1pf(eff));
        float eta = (1.0f + (1.0f - l)) * wb + 0.1f;   // K=1, LAM=0.1
        g_outlier[c] = l - eta;
        g_invEff[c] = 1.0f / fmaxf(1.0f, eff);
        g_Spos[c] = 0.0f;
        g_Sneg[c] = 0.0f;
        g_Nsum[c] = 0.0f;
        if (b == 2560 && tid == 0) g_tileCtr = GRID_MAIN;   // dynamic scheduler seed
    }
}

// ---------------- HMMA helpers ----------------
__device__ __forceinline__ uint32_t smem_u32(const void* p) {
    uint32_t a;
    asm("{ .reg .u64 t; cvta.to.shared.u64 t, %1; cvt.u32.u64 %0, t; }" : "=r"(a) : "l"(p));
    return a;
}
__device__ __forceinline__ void mma16816(float* d, const uint32_t* a, const uint32_t* b) {
    asm volatile(
        "mma.sync.aligned.m16n8k16.row.col.f32.bf16.bf16.f32 "
        "{%0,%1,%2,%3}, {%4,%5,%6,%7}, {%8,%9}, {%0,%1,%2,%3};\n"
        : "+f"(d[0]), "+f"(d[1]), "+f"(d[2]), "+f"(d[3])
        : "r"(a[0]), "r"(a[1]), "r"(a[2]), "r"(a[3]), "r"(b[0]), "r"(b[1]));
}
#define LDSM_X4(r, a) \
    asm volatile("ldmatrix.sync.aligned.m8n8.x4.shared.b16 {%0,%1,%2,%3}, [%4];" \
        : "=r"((r)[0]), "=r"((r)[1]), "=r"((r)[2]), "=r"((r)[3]) : "r"(a))

__device__ __forceinline__ void cpa16(uint32_t s, const void* g) {
    asm volatile("cp.async.cg.shared.global [%0], [%1], 16;" :: "r"(s), "l"(g));
}
#define CP_COMMIT() asm volatile("cp.async.commit_group;" ::: "memory")

// row r (128B rows), 16B granule g (0..7): xor swizzle
#define SWZ(r, g) ((r) * 128 + (((g) ^ ((r) & 7)) << 4))

// ---------------- persistent main HMMA kernel (dynamic tile scheduling) ----------------
// Tiles: 128x128, tile id t: cBase=(t&127)*128, mBase=(t>>7)*128; 1024 tiles.
// Grid = 296 persistent CTAs (2/SM), 256 threads, warp grid 2(M) x 4(N).
// K chunks of 64 (8/tile), 3-stage cp.async ring, prefetch distance 2.
// Tile claims via global atomic (claim at k==3, visible k==4, used k==6).
#define SM_TGT   0       // int [2][128]
#define SM_OUTL  1024    // float [2][128]
#define SM_IE    2048    // float [2][128]
#define SM_STG   3072    // 3 stages x (A 16KB + B 16KB)
#define SM_BYTES 101376

__global__ void __launch_bounds__(256, 2) mainHMMA(const int* __restrict__ targets) {
    extern __shared__ __align__(1024) char sm[];
    __shared__ int sNext;
    const uint32_t smb = smem_u32(sm);
    const int tid = threadIdx.x;
    const int lane = tid & 31;
    const int warp = tid >> 5;
    const int warpM = warp >> 2;   // 0..1 (64 rows each)
    const int warpN = warp & 3;    // 0..3 (32 cols each)

    float acc[4][4][4];
#pragma unroll
    for (int i = 0; i < 4; i++)
#pragma unroll
        for (int j = 0; j < 4; j++)
#pragma unroll
            for (int e = 0; e < 4; e++) acc[i][j][e] = 0.0f;

    // prefetch chunk k_ of tile tt_ into stage sidx_, constants to parity par_
#define PREFETCH_T(tt_, k_, sidx_, par_) do { \
        const int cB_ = ((tt_) & 127) << 7, mB_ = ((tt_) >> 7) << 7; \
        const int kOff_ = (k_) * 64; \
        const uint32_t stg_ = smb + SM_STG + (sidx_) * 32768; \
        _Pragma("unroll") \
        for (int i_ = 0; i_ < 4; i_++) { \
            int idx_ = tid + i_ * 256; int r_ = idx_ >> 3, q_ = idx_ & 7; \
            cpa16(stg_ + SWZ(r_, q_), \
                  g_inputB + (size_t)(mB_ + r_) * E_SZ + kOff_ + q_ * 8); \
        } \
        _Pragma("unroll") \
        for (int i_ = 0; i_ < 4; i_++) { \
            int idx_ = tid + i_ * 256; int r_ = idx_ >> 3, q_ = idx_ & 7; \
            cpa16(stg_ + 16384 + SWZ(r_, q_), \
                  g_proxyB + (size_t)(cB_ + r_) * E_SZ + kOff_ + q_ * 8); \
        } \
        if ((k_) == 0) { \
            int pb_ = (par_) << 9; \
            if (tid < 32)       cpa16(smb + SM_TGT  + pb_ + tid * 16,        targets   + mB_ + tid * 4); \
            else if (tid < 64)  cpa16(smb + SM_OUTL + pb_ + (tid - 32) * 16, g_outlier + cB_ + (tid - 32) * 4); \
            else if (tid < 96)  cpa16(smb + SM_IE   + pb_ + (tid - 64) * 16, g_invEff  + cB_ + (tid - 64) * 4); \
        } \
        CP_COMMIT(); \
    } while (0)

    int cur = blockIdx.x;   // first tile: static seed
    int nxt = NTILES;       // sentinel until claimed
    int curPar = 0;
    int gg = 0;             // global chunk counter (stage rotation)
    int k = 0;              // chunk within current tile

    PREFETCH_T(cur, 0, 0, 0);
    PREFETCH_T(cur, 1, 1, 0);

#pragma unroll 1
    while (true) {
        asm volatile("cp.async.wait_group 1;" ::: "memory");
        __syncthreads();

        if (k == 4) nxt = sNext;   // claimed at k==3, published by the sync above

        // prefetch chunk k+2 (crosses into next tile at k>=6)
        {
            int pk = k + 2;
            if (pk < 8) {
                PREFETCH_T(cur, pk, (gg + 2) % 3, curPar);
            } else {
                int pt = (nxt < NTILES) ? nxt : 0;   // clamp: harmless traffic at the end
                PREFETCH_T(pt, pk - 8, (gg + 2) % 3, curPar ^ 1);
            }
        }
        if (k == 3 && tid == 0) sNext = atomicAdd(&g_tileCtr, 1u);

        const uint32_t aBase = smb + SM_STG + (gg % 3) * 32768;
        const uint32_t bBase = aBase + 16384;
#pragma unroll
        for (int ks = 0; ks < 4; ks++) {
            uint32_t a[4][4], bfr[2][4];
#pragma unroll
            for (int mt = 0; mt < 4; mt++) {
                int r = warpM * 64 + mt * 16 + (lane & 15);
                int q = ks * 2 + (lane >> 4);
                LDSM_X4(a[mt], aBase + SWZ(r, q));
            }
#pragma unroll
            for (int np = 0; np < 2; np++) {
                int n = warpN * 32 + np * 16 + ((lane >> 4) << 3) + (lane & 7);
                int q = ks * 2 + ((lane >> 3) & 1);
                LDSM_X4(bfr[np], bBase + SWZ(n, q));
            }
#pragma unroll
            for (int mt = 0; mt < 4; mt++)
#pragma unroll
                for (int nt = 0; nt < 4; nt++)
                    mma16816(acc[mt][nt], a[mt], &bfr[nt >> 1][(nt & 1) * 2]);
        }

        if (k == 7) {
            // ---- epilogue for tile cur ----
            const int cBase = (cur & 127) << 7;
            const int par = curPar << 7;
            const int* shTgt = (const int*)(sm + SM_TGT) + par;
            const float* shOutl = (const float*)(sm + SM_OUTL) + par;
            const float* shIE = (const float*)(sm + SM_IE) + par;

            int tg[4][2];
#pragma unroll
            for (int mt = 0; mt < 4; mt++) {
                int rl = warpM * 64 + mt * 16 + (lane >> 2);
                tg[mt][0] = shTgt[rl];
                tg[mt][1] = shTgt[rl + 8];
            }
#pragma unroll
            for (int nt = 0; nt < 4; nt++) {
#pragma unroll
                for (int p = 0; p < 2; p++) {
                    int cc = warpN * 32 + nt * 8 + (lane & 3) * 2 + p;
                    float outl = shOutl[cc];
                    float ie = shIE[cc];
                    float s1 = A_L2E * ie,  c1 = s1 * 0.1f;    // nv = ie
                    const float s0 = A_L2E, c0 = A_L2E * 0.1f; // nv = 1
                    int clsG = cBase + cc;
                    float sP = 0.0f, sN = 0.0f, sV = 0.0f;
#pragma unroll
                    for (int mt = 0; mt < 4; mt++) {
#pragma unroll
                        for (int h = 0; h < 2; h++) {
                            float cv = acc[mt][nt][h * 2 + p];
                            if (tg[mt][h] == clsG) {
                                sP += ex2(fmaf(-A_L2E, cv, c0));   // 32*(0.1-cv)*log2e
                            } else {
                                bool low = (cv < outl);
                                sV += low ? ie : 1.0f;
                                float xr = low ? fmaf(s1, cv, c1) : fmaf(s0, cv, c0);
                                sN += ex2(xr);
                            }
                        }
                    }
#pragma unroll
                    for (int o = 4; o <= 16; o <<= 1) {
                        sP += __shfl_xor_sync(0xffffffffu, sP, o);
                        sN += __shfl_xor_sync(0xffffffffu, sN, o);
                        sV += __shfl_xor_sync(0xffffffffu, sV, o);
                    }
                    if ((lane >> 2) == 0) {
                        atomicAdd(&g_Spos[clsG], sP);
                        atomicAdd(&g_Sneg[clsG], sN);
                        atomicAdd(&g_Nsum[clsG], sV);
                    }
                }
            }
#pragma unroll
            for (int i = 0; i < 4; i++)
#pragma unroll
                for (int j = 0; j < 4; j++)
#pragma unroll
                    for (int e = 0; e < 4; e++) acc[i][j][e] = 0.0f;

            cur = nxt;
            curPar ^= 1;
            k = 0; gg++;
            if (cur >= NTILES) break;
        } else {
            k++; gg++;
        }
    }
}

// ---------------- finalize (single block: race-free shared histogram) ----------------
#define FIN_SMEM (C_SZ * 4)
__global__ void __launch_bounds__(1024) finalizeKernel(const int* __restrict__ targets,
                                                       float* __restrict__ out) {
    extern __shared__ int scnt[];
    __shared__ float smr[4][1024];
    int tid = threadIdx.x;
    for (int c = tid; c < C_SZ; c += 1024) scnt[c] = 0;
    __syncthreads();
    atomicAdd(&scnt[targets[tid]], 1);   // blockDim == B_SZ == 1024
    __syncthreads();

    float posT = 0.0f, negT = 0.0f, posW = 0.0f, negW = 0.0f;
    for (int c = tid; c < C_SZ; c += 1024) {
        int cnt = scnt[c];
        if (cnt > 0) { posW += 1.0f; posT += flog1p(g_Spos[c]); }
        negT += flog1p(g_Sneg[c]);
        int Ncnt = B_SZ - cnt;
        float nm = g_Nsum[c] / fmaxf((float)Ncnt, 1.0f);
        if (Ncnt > 0) negW += nm;
    }
    smr[0][tid] = posT; smr[1][tid] = negT; smr[2][tid] = posW; smr[3][tid] = negW;
    __syncthreads();
    for (int s = 512; s > 0; s >>= 1) {
        if (tid < s) {
#pragma unroll
            for (int j = 0; j < 4; j++) smr[j][tid] += smr[j][tid + s];
        }
        __syncthreads();
    }
    if (tid == 0) out[0] = smr[0][0] / smr[2][0] + smr[1][0] / smr[3][0];
}

// ---------------- launch ----------------
extern "C" void kernel_launch(void* const* d_in, const int* in_sizes, int n_in,
                              void* d_out, int out_size) {
    const float* inputs  = (const float*)d_in[0];   // [B,E] f32
    const int*   targets = (const int*)d_in[1];     // [B]   i32
    const float* proxies = (const float*)d_in[2];   // [C,E] f32
    const float* effN    = (const float*)d_in[3];   // [C]
    const float* ls      = (const float*)d_in[4];   // [C]
    float* out = (float*)d_out;

    cudaFuncSetAttribute(mainHMMA, cudaFuncAttributeMaxDynamicSharedMemorySize, SM_BYTES);
    cudaFuncSetAttribute(finalizeKernel, cudaFuncAttributeMaxDynamicSharedMemorySize, FIN_SMEM);

    prepKernel<<<2624, 256>>>(inputs, proxies, effN, ls);
    mainHMMA<<<GRID_MAIN, 256, SM_BYTES>>>(targets);
    finalizeKernel<<<1, 1024, FIN_SMEM>>>(targets, out);
}

// round 13
// speedup vs baseline: 2.2345x; 1.0041x over previous
#include <cuda_runtime.h>
#include <cuda_bf16.h>
#include <cstdint>

#define B_SZ 1024
#define E_SZ 512
#define C_SZ 16384

// ---------------- scratch: chunk-major pre-swizzled tile images ----------------
// g_proxyQ: [128 cTiles][8 chunks][16384B]  (exact smem image, SW-xor applied)
// g_inputQ: [8 mGroups][8 chunks][16384B]
__device__ __align__(16) char g_proxyQ[(size_t)C_SZ * E_SZ * 2];
__device__ __align__(16) char g_inputQ[(size_t)B_SZ * E_SZ * 2];
__device__ float g_outlier[C_SZ];
__device__ float g_invEff[C_SZ];
__device__ float g_Spos[C_SZ];
__device__ float g_Sneg[C_SZ];
__device__ float g_Nsum[C_SZ];
__device__ unsigned g_tileCtr;

// exp(32*(...)) via MUFU.EX2
__device__ __forceinline__ float ex2(float x) {
    float r;
    asm("ex2.approx.f32 %0, %1;" : "=f"(r) : "f"(x));
    return r;
}
#define A_L2E 46.166241308446828f   // 32 * log2(e)

__device__ __forceinline__ float flog1p(float x) {
    float r;
    asm("lg2.approx.f32 %0, %1;" : "=f"(r) : "f"(1.0f + x));
    return 0.693147180559945f * r;
}

#define GRID_MAIN 296
#define NTILES    1024

// ---------------- fused prep kernel ----------------
// blocks 0..2175  : row normalize + bf16, write chunk-major swizzled image
//                   rows 0..16383 proxies (L2-normalized), 16384..17407 inputs (copy)
// blocks 2176..2239: per-class constants + accumulator zero
__global__ void __launch_bounds__(256) prepKernel(
    const float* __restrict__ inputs,
    const float* __restrict__ proxies, const float* __restrict__ effN,
    const float* __restrict__ ls)
{
    const int b = blockIdx.x;
    const int tid = threadIdx.x;
    if (b < 2176) {
        int row = b * 8 + (tid >> 5);
        int lane = tid & 31;
        bool isProxy = row < C_SZ;
        int drow = isProxy ? row : row - C_SZ;
        const float4* p4 = (const float4*)((isProxy ? proxies : inputs) + (size_t)drow * E_SZ);
        float4 v[4];
        float s = 0.0f;
#pragma unroll
        for (int j = 0; j < 4; j++) {
            v[j] = p4[lane + j * 32];
            s += v[j].x * v[j].x + v[j].y * v[j].y + v[j].z * v[j].z + v[j].w * v[j].w;
        }
        float rn = 1.0f;
        if (isProxy) {
#pragma unroll
            for (int o = 16; o > 0; o >>= 1) s += __shfl_xor_sync(0xffffffffu, s, o);
            rn = rsqrtf(s + 1e-12f);
        }
        int grp = drow >> 7, lr = drow & 127;
        char* base = (isProxy ? g_proxyQ : g_inputQ) + ((size_t)grp * 8) * 16384;
#pragma unroll
        for (int j = 0; j < 4; j++) {
            __nv_bfloat162 lo = __floats2bfloat162_rn(v[j].x * rn, v[j].y * rn);
            __nv_bfloat162 hi = __floats2bfloat162_rn(v[j].z * rn, v[j].w * rn);
            uint2 pk;
            pk.x = *(uint32_t*)&lo;
            pk.y = *(uint32_t*)&hi;
            int g4 = lane + j * 32;          // float4 granule 0..127 (4 f32 = 8 output bytes)
            int kch = g4 >> 4;               // chunk (64 cols each)
            int rem = g4 & 15;
            int q = rem >> 1;                // 16B granule within 128B chunk-row
            int sub = (g4 & 1) * 8;
            *(uint2*)(base + kch * 16384 + lr * 128 + (((q ^ (lr & 7)) << 4) | sub)) = pk;
        }
    } else {
        int c = (b - 2176) * 256 + tid;
        float eff = effN[c], l = ls[c];
        float wb = 1.0f / (1.0f + log1pf(eff));
        float eta = (1.0f + (1.0f - l)) * wb + 0.1f;   // K=1, LAM=0.1
        g_outlier[c] = l - eta;
        g_invEff[c] = 1.0f / fmaxf(1.0f, eff);
        g_Spos[c] = 0.0f;
        g_Sneg[c] = 0.0f;
        g_Nsum[c] = 0.0f;
        if (b == 2176 && tid == 0) g_tileCtr = GRID_MAIN;
    }
}

// ---------------- HMMA / async helpers ----------------
__device__ __forceinline__ uint32_t smem_u32(const void* p) {
    uint32_t a;
    asm("{ .reg .u64 t; cvta.to.shared.u64 t, %1; cvt.u32.u64 %0, t; }" : "=r"(a) : "l"(p));
    return a;
}
__device__ __forceinline__ void mma16816(float* d, const uint32_t* a, const uint32_t* b) {
    asm volatile(
        "mma.sync.aligned.m16n8k16.row.col.f32.bf16.bf16.f32 "
        "{%0,%1,%2,%3}, {%4,%5,%6,%7}, {%8,%9}, {%0,%1,%2,%3};\n"
        : "+f"(d[0]), "+f"(d[1]), "+f"(d[2]), "+f"(d[3])
        : "r"(a[0]), "r"(a[1]), "r"(a[2]), "r"(a[3]), "r"(b[0]), "r"(b[1]));
}
#define LDSM_X4(r, a) \
    asm volatile("ldmatrix.sync.aligned.m8n8.x4.shared.b16 {%0,%1,%2,%3}, [%4];" \
        : "=r"((r)[0]), "=r"((r)[1]), "=r"((r)[2]), "=r"((r)[3]) : "r"(a))

__device__ __forceinline__ void cpa16(uint32_t s, const void* g) {
    asm volatile("cp.async.cg.shared.global [%0], [%1], 16;" :: "r"(s), "l"(g));
}
#define CP_COMMIT() asm volatile("cp.async.commit_group;" ::: "memory")

__device__ __forceinline__ void bulkcp(uint32_t dst, const void* src, uint32_t bytes, uint32_t mbar) {
    asm volatile(
        "cp.async.bulk.shared::cluster.global.mbarrier::complete_tx::bytes [%0], [%1], %2, [%3];"
        :: "r"(dst), "l"(src), "r"(bytes), "r"(mbar) : "memory");
}
__device__ __forceinline__ void mbar_init(uint32_t mbar, uint32_t cnt) {
    asm volatile("mbarrier.init.shared.b64 [%0], %1;" :: "r"(mbar), "r"(cnt) : "memory");
}
__device__ __forceinline__ void mbar_expect(uint32_t mbar, uint32_t bytes) {
    asm volatile("mbarrier.arrive.expect_tx.shared.b64 _, [%0], %1;" :: "r"(mbar), "r"(bytes) : "memory");
}
__device__ __forceinline__ void mbar_wait(uint32_t mbar, uint32_t parity) {
    asm volatile(
        "{\n\t.reg .pred P;\n"
        "WL_%=:\n\t"
        "mbarrier.try_wait.parity.acquire.cta.shared::cta.b64 P, [%0], %1, 0x989680;\n\t"
        "@P bra.uni WD_%=;\n\t"
        "bra.uni WL_%=;\n"
        "WD_%=:\n\t}"
        :: "r"(mbar), "r"(parity) : "memory");
}

// row r (128B rows), 16B granule g (0..7): xor swizzle
#define SWZ(r, g) ((r) * 128 + (((g) ^ ((r) & 7)) << 4))

// ---------------- persistent main HMMA kernel (bulk-copy pipeline) ----------------
#define SM_TGT   0       // int [2][128]
#define SM_OUTL  1024    // float [2][128]
#define SM_IE    2048    // float [2][128]
#define SM_MBAR  3072    // 3 x 8B
#define SM_STG   4096    // 3 stages x (A 16KB + B 16KB)
#define SM_BYTES 102400

__global__ void __launch_bounds__(256, 2) mainHMMA(const int* __restrict__ targets) {
    extern __shared__ __align__(1024) char sm[];
    __shared__ int sNext;
    const uint32_t smb = smem_u32(sm);
    const int tid = threadIdx.x;
    const int lane = tid & 31;
    const int warp = tid >> 5;
    const int warpM = warp >> 2;   // 0..1 (64 rows each)
    const int warpN = warp & 3;    // 0..3 (32 cols each)

    if (tid == 0) {
        mbar_init(smb + SM_MBAR, 1);
        mbar_init(smb + SM_MBAR + 8, 1);
        mbar_init(smb + SM_MBAR + 16, 1);
    }
    __syncthreads();

    float acc[4][4][4];
#pragma unroll
    for (int i = 0; i < 4; i++)
#pragma unroll
        for (int j = 0; j < 4; j++)
#pragma unroll
            for (int e = 0; e < 4; e++) acc[i][j][e] = 0.0f;

    // prefetch chunk k_ of tile tt_ into stage sidx_; constants at k_==0 -> parity par_
#define PREFETCH_T(tt_, k_, sidx_, par_) do { \
        if (tid == 0) { \
            uint32_t mb_ = smb + SM_MBAR + (sidx_) * 8; \
            mbar_expect(mb_, 32768u); \
            uint32_t stg_ = smb + SM_STG + (sidx_) * 32768; \
            bulkcp(stg_,         g_inputQ + ((((size_t)(tt_) >> 7) * 8 + (k_)) << 14), 16384u, mb_); \
            bulkcp(stg_ + 16384, g_proxyQ + ((((size_t)(tt_) & 127) * 8 + (k_)) << 14), 16384u, mb_); \
        } \
        if ((k_) == 0) { \
            const int cB_ = ((tt_) & 127) << 7, mB_ = ((tt_) >> 7) << 7; \
            int pb_ = (par_) << 9; \
            if (tid < 32)       cpa16(smb + SM_TGT  + pb_ + tid * 16,        targets   + mB_ + tid * 4); \
            else if (tid < 64)  cpa16(smb + SM_OUTL + pb_ + (tid - 32) * 16, g_outlier + cB_ + (tid - 32) * 4); \
            else if (tid < 96)  cpa16(smb + SM_IE   + pb_ + (tid - 64) * 16, g_invEff  + cB_ + (tid - 64) * 4); \
            CP_COMMIT(); \
        } \
    } while (0)

    int cur = blockIdx.x;   // first tile: static seed
    int nxt = NTILES;       // sentinel until claimed
    int curPar = 0;
    int k = 0;              // chunk within current tile
    int gm = 0, g3 = 0;     // stage index (gg%3) and phase parity ((gg/3)&1)

    PREFETCH_T(cur, 0, 0, 0);
    PREFETCH_T(cur, 1, 1, 0);

#pragma unroll 1
    while (true) {
        mbar_wait(smb + SM_MBAR + gm * 8, g3);
        __syncthreads();   // all warps done with stage (gm+2)%3's old contents

        if (k == 4) nxt = sNext;

        {
            int pk = k + 2;
            int s2 = gm + 2; if (s2 >= 3) s2 -= 3;
            if (pk < 8)               PREFETCH_T(cur, pk, s2, curPar);
            else if (nxt < NTILES)    PREFETCH_T(nxt, pk - 8, s2, curPar ^ 1);
        }
        if (k == 3 && tid == 0) sNext = atomicAdd(&g_tileCtr, 1u);

        const uint32_t aBase = smb + SM_STG + gm * 32768;
        const uint32_t bBase = aBase + 16384;
#pragma unroll
        for (int ks = 0; ks < 4; ks++) {
            uint32_t a[4][4], bfr[2][4];
#pragma unroll
            for (int mt = 0; mt < 4; mt++) {
                int r = warpM * 64 + mt * 16 + (lane & 15);
                int q = ks * 2 + (lane >> 4);
                LDSM_X4(a[mt], aBase + SWZ(r, q));
            }
#pragma unroll
            for (int np = 0; np < 2; np++) {
                int n = warpN * 32 + np * 16 + ((lane >> 4) << 3) + (lane & 7);
                int q = ks * 2 + ((lane >> 3) & 1);
                LDSM_X4(bfr[np], bBase + SWZ(n, q));
            }
#pragma unroll
            for (int mt = 0; mt < 4; mt++)
#pragma unroll
                for (int nt = 0; nt < 4; nt++)
                    mma16816(acc[mt][nt], a[mt], &bfr[nt >> 1][(nt & 1) * 2]);
        }

        if (k == 7) {
            // constants for this tile were cp.async'd ≥7 chunks ago; make them visible
            asm volatile("cp.async.wait_group 0;" ::: "memory");
            __syncthreads();

            const int cBase = (cur & 127) << 7;
            const int par = curPar << 7;
            const int* shTgt = (const int*)(sm + SM_TGT) + par;
            const float* shOutl = (const float*)(sm + SM_OUTL) + par;
            const float* shIE = (const float*)(sm + SM_IE) + par;

            int tg[4][2];
#pragma unroll
            for (int mt = 0; mt < 4; mt++) {
                int rl = warpM * 64 + mt * 16 + (lane >> 2);
                tg[mt][0] = shTgt[rl];
                tg[mt][1] = shTgt[rl + 8];
            }
#pragma unroll
            for (int nt = 0; nt < 4; nt++) {
#pragma unroll
                for (int p = 0; p < 2; p++) {
                    int cc = warpN * 32 + nt * 8 + (lane & 3) * 2 + p;
                    float outl = shOutl[cc];
                    float ie = shIE[cc];
                    float s1 = A_L2E * ie,  c1 = s1 * 0.1f;    // nv = ie
                    const float s0 = A_L2E, c0 = A_L2E * 0.1f; // nv = 1
                    int clsG = cBase + cc;
                    float sP = 0.0f, sN = 0.0f, sV = 0.0f;
#pragma unroll
                    for (int mt = 0; mt < 4; mt++) {
#pragma unroll
                        for (int h = 0; h < 2; h++) {
                            float cv = acc[mt][nt][h * 2 + p];
                            if (tg[mt][h] == clsG) {
                                sP += ex2(fmaf(-A_L2E, cv, c0));
                            } else {
                                bool low = (cv < outl);
                                sV += low ? ie : 1.0f;
                                float xr = low ? fmaf(s1, cv, c1) : fmaf(s0, cv, c0);
                                sN += ex2(xr);
                            }
                        }
                    }
#pragma unroll
                    for (int o = 4; o <= 16; o <<= 1) {
                        sP += __shfl_xor_sync(0xffffffffu, sP, o);
                        sN += __shfl_xor_sync(0xffffffffu, sN, o);
                        sV += __shfl_xor_sync(0xffffffffu, sV, o);
                    }
                    if ((lane >> 2) == 0) {
                        atomicAdd(&g_Spos[clsG], sP);
                        atomicAdd(&g_Sneg[clsG], sN);
                        atomicAdd(&g_Nsum[clsG], sV);
                    }
                }
            }
#pragma unroll
            for (int i = 0; i < 4; i++)
#pragma unroll
                for (int j = 0; j < 4; j++)
#pragma unroll
                    for (int e = 0; e < 4; e++) acc[i][j][e] = 0.0f;

            cur = nxt;
            curPar ^= 1;
            k = 0;
            if (++gm == 3) { gm = 0; g3 ^= 1; }
            if (cur >= NTILES) break;
        } else {
            k++;
            if (++gm == 3) { gm = 0; g3 ^= 1; }
        }
    }
}

// ---------------- finalize (single block: race-free shared histogram) ----------------
#define FIN_SMEM (C_SZ * 4)
__global__ void __launch_bounds__(1024) finalizeKernel(const int* __restrict__ targets,
                                                       float* __restrict__ out) {
    extern __shared__ int scnt[];
    __shared__ float smr[4][1024];
    int tid = threadIdx.x;
    for (int c = tid; c < C_SZ; c += 1024) scnt[c] = 0;
    __syncthreads();
    atomicAdd(&scnt[targets[tid]], 1);   // blockDim == B_SZ == 1024
    __syncthreads();

    float posT = 0.0f, negT = 0.0f, posW = 0.0f, negW = 0.0f;
    for (int c = tid; c < C_SZ; c += 1024) {
        int cnt = scnt[c];
        if (cnt > 0) { posW += 1.0f; posT += flog1p(g_Spos[c]); }
        negT += flog1p(g_Sneg[c]);
        int Ncnt = B_SZ - cnt;
        float nm = g_Nsum[c] / fmaxf((float)Ncnt, 1.0f);
        if (Ncnt > 0) negW += nm;
    }
    smr[0][tid] = posT; smr[1][tid] = negT; smr[2][tid] = posW; smr[3][tid] = negW;
    __syncthreads();
    for (int s = 512; s > 0; s >>= 1) {
        if (tid < s) {
#pragma unroll
            for (int j = 0; j < 4; j++) smr[j][tid] += smr[j][tid + s];
        }
        __syncthreads();
    }
    if (tid == 0) out[0] = smr[0][0] / smr[2][0] + smr[1][0] / smr[3][0];
}

// ---------------- launch ----------------
extern "C" void kernel_launch(void* const* d_in, const int* in_sizes, int n_in,
                              void* d_out, int out_size) {
    const float* inputs  = (const float*)d_in[0];   // [B,E] f32
    const int*   targets = (const int*)d_in[1];     // [B]   i32
    const float* proxies = (const float*)d_in[2];   // [C,E] f32
    const float* effN    = (const float*)d_in[3];   // [C]
    const float* ls      = (const float*)d_in[4];   // [C]
    float* out = (float*)d_out;

    cudaFuncSetAttribute(mainHMMA, cudaFuncAttributeMaxDynamicSharedMemorySize, SM_BYTES);
    cudaFuncSetAttribute(finalizeKernel, cudaFuncAttributeMaxDynamicSharedMemorySize, FIN_SMEM);

    prepKernel<<<2240, 256>>>(inputs, proxies, effN, ls);
    mainHMMA<<<GRID_MAIN, 256, SM_BYTES>>>(targets);
    finalizeKernel<<<1, 1024, FIN_SMEM>>>(targets, out);
}